// round 13
// baseline (speedup 1.0000x reference)
#include <cuda_runtime.h>
#include <cuda_bf16.h>
#include <cuda_fp16.h>
#include <cstdint>
#include <cstddef>

#define NBAT 128
#define NTIME 256
#define NCH 512
#define HDIM 512
#define BT (NBAT*NTIME)
#define NSTEPS 32
#define NOUT 96
#define GRID 128
#define NTHR 512
#define SAS 40

// ------------------------- device scratch -------------------------
__device__ __align__(16) __half g_fp16[(size_t)BT*HDIM];          // feats_proj fp16 [b][t][h]
__device__ __align__(16) __half g_f16ctx[(size_t)NBAT*NCH*NTIME]; // feats fp16 [b][c][t]
__device__ __align__(16) __half g_A0f16[(size_t)BT*NCH];
__device__ __align__(16) __half g_Wi2h16[HDIM*NCH];
__device__ __align__(16) __half g_Wh2hT16[HDIM*HDIM];             // TRANSPOSED [k][j]
__device__ __align__(16) __nv_bfloat16 g_h_h[NBAT*HDIM], g_h_l[NBAT*HDIM];
__device__ __align__(16) __nv_bfloat16 g_Wih_h[3*HDIM*NCH],  g_Wih_l[3*HDIM*NCH];
__device__ __align__(16) __nv_bfloat16 g_Whh_h[3*HDIM*HDIM], g_Whh_l[3*HDIM*HDIM];
__device__ __align__(16) __nv_bfloat16 g_Wgen_h[NOUT*HDIM],  g_Wgen_l[NOUT*HDIM];
__device__ __align__(16) __nv_bfloat16 g_ctx_h[NBAT*NCH], g_ctx_l[NBAT*NCH];
__device__ __align__(16) __nv_bfloat16 g_hid_h[(size_t)NBAT*NSTEPS*HDIM];
__device__ __align__(16) __nv_bfloat16 g_hid_l[(size_t)NBAT*NSTEPS*HDIM];
__device__ float g_gpart[2*6*NBAT*HDIM];      // [kz][gate][row][col]
__device__ unsigned g_bar;

// ------------------------- helpers -------------------------
__device__ __forceinline__ void mma16816(float* c,
    uint32_t a0, uint32_t a1, uint32_t a2, uint32_t a3, uint32_t b0, uint32_t b1)
{
    asm volatile(
        "mma.sync.aligned.m16n8k16.row.col.f32.bf16.bf16.f32 "
        "{%0,%1,%2,%3}, {%4,%5,%6,%7}, {%8,%9}, {%0,%1,%2,%3};\n"
        : "+f"(c[0]), "+f"(c[1]), "+f"(c[2]), "+f"(c[3])
        : "r"(a0), "r"(a1), "r"(a2), "r"(a3), "r"(b0), "r"(b1));
}

__device__ __forceinline__ void mma16816_f16(float* c,
    uint32_t a0, uint32_t a1, uint32_t a2, uint32_t a3, uint32_t b0, uint32_t b1)
{
    asm volatile(
        "mma.sync.aligned.m16n8k16.row.col.f32.f16.f16.f32 "
        "{%0,%1,%2,%3}, {%4,%5,%6,%7}, {%8,%9}, {%0,%1,%2,%3};\n"
        : "+f"(c[0]), "+f"(c[1]), "+f"(c[2]), "+f"(c[3])
        : "r"(a0), "r"(a1), "r"(a2), "r"(a3), "r"(b0), "r"(b1));
}

__device__ __forceinline__ void ldsm_x4(uint32_t& r0, uint32_t& r1, uint32_t& r2, uint32_t& r3,
                                        uint32_t addr)
{
    asm volatile("ldmatrix.sync.aligned.m8n8.x4.shared.b16 {%0,%1,%2,%3}, [%4];"
        : "=r"(r0), "=r"(r1), "=r"(r2), "=r"(r3) : "r"(addr));
}

__device__ __forceinline__ void ldsm_x2(uint32_t& r0, uint32_t& r1, uint32_t addr)
{
    asm volatile("ldmatrix.sync.aligned.m8n8.x2.shared.b16 {%0,%1}, [%2];"
        : "=r"(r0), "=r"(r1) : "r"(addr));
}

__device__ __forceinline__ void split_val(float v, __nv_bfloat16& hi, __nv_bfloat16& lo)
{
    hi = __float2bfloat16_rn(v);
    lo = __float2bfloat16_rn(v - __bfloat162float(hi));
}

__device__ __forceinline__ float warp_sum(float v)
{
    #pragma unroll
    for (int o = 16; o > 0; o >>= 1) v += __shfl_xor_sync(0xffffffffu, v, o);
    return v;
}

__device__ __forceinline__ float warp_max(float v)
{
    #pragma unroll
    for (int o = 16; o > 0; o >>= 1) v = fmaxf(v, __shfl_xor_sync(0xffffffffu, v, o));
    return v;
}

__device__ __forceinline__ float tanh_ap(float x)
{
    float y;
    asm("tanh.approx.f32 %0, %1;" : "=f"(y) : "f"(x));
    return y;
}

__device__ __forceinline__ void cp16(void* d, const void* s)     // .ca
{
    uint32_t ds = (uint32_t)__cvta_generic_to_shared(d);
    asm volatile("cp.async.ca.shared.global [%0], [%1], 16;\n" :: "r"(ds), "l"(s));
}
__device__ __forceinline__ void cp16cg(void* d, const void* s)   // .cg (cross-phase)
{
    uint32_t ds = (uint32_t)__cvta_generic_to_shared(d);
    asm volatile("cp.async.cg.shared.global [%0], [%1], 16;\n" :: "r"(ds), "l"(s));
}
__device__ __forceinline__ void cp_commit() { asm volatile("cp.async.commit_group;\n"); }
__device__ __forceinline__ void cp_wait1()  { asm volatile("cp.async.wait_group 1;\n"); }
__device__ __forceinline__ void cp_wait0()  { asm volatile("cp.async.wait_group 0;\n"); }

// ------------------------- prologue -------------------------
__global__ void fused_split(const float* __restrict__ W0, const float* __restrict__ W1,
                            const float* __restrict__ W2, const float* __restrict__ W3,
                            const float* __restrict__ W4)
{
    const int n0 = HDIM*NCH;
    const int n1 = n0 + HDIM*HDIM;
    const int n2 = n1 + 3*HDIM*NCH;
    const int n3 = n2 + 3*HDIM*HDIM;
    const int n4 = n3 + NOUT*HDIM;
    int i = blockIdx.x * 256 + threadIdx.x;
    if (i >= n4) return;
    if (i < n0)      { g_Wi2h16[i] = __float2half(W0[i]); return; }
    if (i < n1) {
        const int off = i - n0;
        const int j = off >> 9;          // Wh2h row
        const int k = off & 511;         // Wh2h col
        g_Wh2hT16[k*HDIM + j] = __float2half(W1[off]);   // transposed store
        return;
    }
    const float* src; __nv_bfloat16 *dh, *dl; int off;
    if (i < n2)      { src = W2; dh = g_Wih_h;  dl = g_Wih_l;  off = i - n1; }
    else if (i < n3) { src = W3; dh = g_Whh_h;  dl = g_Whh_l;  off = i - n2; }
    else             { src = W4; dh = g_Wgen_h; dl = g_Wgen_l; off = i - n3; }
    __nv_bfloat16 h, l;
    split_val(src[off], h, l);
    dh[off] = h; dl[off] = l;
}

__global__ void transpose_kernel(const float* __restrict__ feats)
{
    __shared__ float tile[32][33];
    int m0 = blockIdx.x * 32;
    int c0 = blockIdx.y * 32;
    int tx = threadIdx.x, ty = threadIdx.y;
    #pragma unroll
    for (int i = ty; i < 32; i += 8)
        tile[i][tx] = feats[(size_t)(c0 + i) * BT + m0 + tx];
    __syncthreads();
    #pragma unroll
    for (int i = ty; i < 32; i += 8)
        g_A0f16[(size_t)(m0 + i) * NCH + c0 + tx] = __float2half(tile[tx][i]);
}

__global__ void feats16_zero_kernel(const float* __restrict__ feats)
{
    size_t idx = (size_t)blockIdx.x * 256 + threadIdx.x;
    int t = idx & (NTIME - 1);
    int c = (idx >> 8) & (NCH - 1);
    int b = (int)(idx >> 17);
    g_f16ctx[idx] = __float2half(feats[((size_t)c * NBAT + b) * NTIME + t]);
    if (idx < NBAT*HDIM) {
        g_h_h[idx] = __float2bfloat16(0.f);
        g_h_l[idx] = __float2bfloat16(0.f);
    }
    if (idx == 0) g_bar = 0u;
}

// ------------------------- GEMM0: fp16, block 128x128, warp 64x64 -------------------------
__global__ void __launch_bounds__(128) gemm_f16b(
    const __half* __restrict__ A, const __half* __restrict__ B,
    __half* __restrict__ C16, int M, int N, int K)
{
    __shared__ __align__(16) __half sA[2][128*SAS], sB[2][128*SAS];

    const int mbase = blockIdx.y * 128;
    const int nbase = blockIdx.x * 128;
    const int tid = threadIdx.x;
    const int warp = tid >> 5, lane = tid & 31;
    const int wm = (warp >> 1) * 64;
    const int wn = (warp & 1) * 64;
    const int gid = lane >> 2, tig = lane & 3;

    const int aRow = wm + (lane & 15);
    const int aCol = (lane >> 4) * 8;
    const int bRow = wn + (lane & 7) + ((lane & 16) ? 8 : 0);
    const int bCol = (lane & 8) ? 8 : 0;

    uint32_t aB[2], bB[2];
    #pragma unroll
    for (int s = 0; s < 2; s++) {
        aB[s] = (uint32_t)__cvta_generic_to_shared(&sA[s][aRow*SAS + aCol]);
        bB[s] = (uint32_t)__cvta_generic_to_shared(&sB[s][bRow*SAS + bCol]);
    }

    float acc[4][8][4];
    #pragma unroll
    for (int a = 0; a < 4; a++)
        #pragma unroll
        for (int b = 0; b < 8; b++)
            #pragma unroll
            for (int c = 0; c < 4; c++) acc[a][b][c] = 0.f;

    const int niter = K / 32;

    auto issue = [&](int kt, int buf) {
        #pragma unroll
        for (int i = tid; i < 1024; i += 128) {
            const int chunk = i & 3;
            const int r = (i >> 2) & 127;
            const int gk = kt + chunk*8;
            if (i < 512) cp16(&sA[buf][r*SAS + chunk*8], &A[(size_t)(mbase + r) * K + gk]);
            else         cp16(&sB[buf][r*SAS + chunk*8], &B[(size_t)(nbase + r) * K + gk]);
        }
        cp_commit();
    };

    issue(0, 0);
    for (int it = 0; it < niter; it++) {
        if (it + 1 < niter) { issue((it + 1) * 32, (it + 1) & 1); cp_wait1(); }
        else cp_wait0();
        __syncthreads();
        const int bf = it & 1;
        #pragma unroll
        for (int kk = 0; kk < 32; kk += 16) {
            uint32_t a[4][4], b[4][4];
            #pragma unroll
            for (int mf = 0; mf < 4; mf++)
                ldsm_x4(a[mf][0], a[mf][1], a[mf][2], a[mf][3], aB[bf] + (mf*16*SAS + kk)*2);
            #pragma unroll
            for (int nf = 0; nf < 4; nf++)
                ldsm_x4(b[nf][0], b[nf][1], b[nf][2], b[nf][3], bB[bf] + (nf*16*SAS + kk)*2);
            #pragma unroll
            for (int mf = 0; mf < 4; mf++) {
                #pragma unroll
                for (int nf = 0; nf < 4; nf++) {
                    mma16816_f16(acc[mf][nf*2    ], a[mf][0], a[mf][1], a[mf][2], a[mf][3], b[nf][0], b[nf][1]);
                    mma16816_f16(acc[mf][nf*2 + 1], a[mf][0], a[mf][1], a[mf][2], a[mf][3], b[nf][2], b[nf][3]);
                }
            }
        }
        __syncthreads();
    }

    #pragma unroll
    for (int mf = 0; mf < 4; mf++) {
        #pragma unroll
        for (int nf = 0; nf < 8; nf++) {
            const int r = mbase + wm + mf*16 + gid;
            const int c = nbase + wn + nf*8 + tig*2;
            C16[(size_t)(r    )*N + c    ] = __float2half(acc[mf][nf][0]);
            C16[(size_t)(r    )*N + c + 1] = __float2half(acc[mf][nf][1]);
            C16[(size_t)(r + 8)*N + c    ] = __float2half(acc[mf][nf][2]);
            C16[(size_t)(r + 8)*N + c + 1] = __float2half(acc[mf][nf][3]);
        }
    }
}

// ------------------------- bf16x3 GEMM (generator) -------------------------
__global__ void __launch_bounds__(256) gemm_x3(
    const __nv_bfloat16* __restrict__ Ah,  const __nv_bfloat16* __restrict__ Al,
    const __nv_bfloat16* __restrict__ Bh,  const __nv_bfloat16* __restrict__ Bl,
    float* __restrict__ C, const float* __restrict__ bias,
    int M, int N, int K)
{
    __shared__ __align__(16) __nv_bfloat16 sAh[2][64*SAS], sAl[2][64*SAS];
    __shared__ __align__(16) __nv_bfloat16 sBh[2][64*SAS], sBl[2][64*SAS];

    const int mbase = blockIdx.y * 64;
    const int nbase = blockIdx.x * 64;
    const int tid = threadIdx.x;
    const int warp = tid >> 5, lane = tid & 31;
    const int wm  = (warp >> 2) * 32;
    const int wn  = (warp & 3) * 16;
    const int gid = lane >> 2, tig = lane & 3;
    const int lr  = tid >> 2;
    const int lc  = (tid & 3) * 8;

    const int nrow = nbase + lr;
    const int nr = (nrow < N) ? nrow : 0;

    float acc[2][2][4];
    #pragma unroll
    for (int a = 0; a < 2; a++)
        #pragma unroll
        for (int b = 0; b < 2; b++)
            #pragma unroll
            for (int c = 0; c < 4; c++) acc[a][b][c] = 0.f;

    const int niter = K / 32;
    {
        cp16(&sAh[0][lr*SAS + lc], &Ah[(size_t)(mbase + lr) * K + lc]);
        cp16(&sAl[0][lr*SAS + lc], &Al[(size_t)(mbase + lr) * K + lc]);
        cp16(&sBh[0][lr*SAS + lc], &Bh[(size_t)nr * K + lc]);
        cp16(&sBl[0][lr*SAS + lc], &Bl[(size_t)nr * K + lc]);
        cp_commit();
    }

    for (int it = 0; it < niter; it++) {
        if (it + 1 < niter) {
            const int buf = (it + 1) & 1;
            const int gk = (it + 1) * 32 + lc;
            cp16(&sAh[buf][lr*SAS + lc], &Ah[(size_t)(mbase + lr) * K + gk]);
            cp16(&sAl[buf][lr*SAS + lc], &Al[(size_t)(mbase + lr) * K + gk]);
            cp16(&sBh[buf][lr*SAS + lc], &Bh[(size_t)nr * K + gk]);
            cp16(&sBl[buf][lr*SAS + lc], &Bl[(size_t)nr * K + gk]);
            cp_commit();
            cp_wait1();
        } else {
            cp_wait0();
        }
        __syncthreads();
        const int bf = it & 1;

        #pragma unroll
        for (int kk = 0; kk < 32; kk += 16) {
            uint32_t ah[2][4], al[2][4];
            #pragma unroll
            for (int mi = 0; mi < 2; mi++) {
                const int r = wm + mi*16 + gid;
                const int c = kk + tig*2;
                ah[mi][0] = *(const uint32_t*)&sAh[bf][(r    )*SAS + c    ];
                ah[mi][1] = *(const uint32_t*)&sAh[bf][(r + 8)*SAS + c    ];
                ah[mi][2] = *(const uint32_t*)&sAh[bf][(r    )*SAS + c + 8];
                ah[mi][3] = *(const uint32_t*)&sAh[bf][(r + 8)*SAS + c + 8];
                al[mi][0] = *(const uint32_t*)&sAl[bf][(r    )*SAS + c    ];
                al[mi][1] = *(const uint32_t*)&sAl[bf][(r + 8)*SAS + c    ];
                al[mi][2] = *(const uint32_t*)&sAl[bf][(r    )*SAS + c + 8];
                al[mi][3] = *(const uint32_t*)&sAl[bf][(r + 8)*SAS + c + 8];
            }
            #pragma unroll
            for (int ni = 0; ni < 2; ni++) {
                const int n = wn + ni*8 + gid;
                const int c = kk + tig*2;
                const uint32_t b0h = *(const uint32_t*)&sBh[bf][n*SAS + c    ];
                const uint32_t b1h = *(const uint32_t*)&sBh[bf][n*SAS + c + 8];
                const uint32_t b0l = *(const uint32_t*)&sBl[bf][n*SAS + c    ];
                const uint32_t b1l = *(const uint32_t*)&sBl[bf][n*SAS + c + 8];
                #pragma unroll
                for (int mi = 0; mi < 2; mi++) {
                    mma16816(acc[mi][ni], ah[mi][0], ah[mi][1], ah[mi][2], ah[mi][3], b0h, b1h);
                    mma16816(acc[mi][ni], ah[mi][0], ah[mi][1], ah[mi][2], ah[mi][3], b0l, b1l);
                    mma16816(acc[mi][ni], al[mi][0], al[mi][1], al[mi][2], al[mi][3], b0h, b1h);
                }
            }
        }
        __syncthreads();
    }

    #pragma unroll
    for (int mi = 0; mi < 2; mi++) {
        #pragma unroll
        for (int ni = 0; ni < 2; ni++) {
            const int r = mbase + wm + mi*16 + gid;
            const int c = nbase + wn + ni*8 + tig*2;
            float b0 = 0.f, b1 = 0.f;
            if (bias != nullptr) {
                if (c     < N) b0 = bias[c];
                if (c + 1 < N) b1 = bias[c + 1];
            }
            if (c < N) {
                C[(size_t)(r    )*N + c] = acc[mi][ni][0] + b0;
                C[(size_t)(r + 8)*N + c] = acc[mi][ni][2] + b0;
            }
            if (c + 1 < N) {
                C[(size_t)(r    )*N + c + 1] = acc[mi][ni][1] + b1;
                C[(size_t)(r + 8)*N + c + 1] = acc[mi][ni][3] + b1;
            }
        }
    }
}

// ------------------------- persistent decode kernel: B | bar | C | bar | D(+GEMV) -------------------------
#define GRU_A_ELE (4*64*SAS)
#define GRU_B_ELE (12*16*SAS)
#define GRU_STAGE (GRU_A_ELE + GRU_B_ELE)
#define PSMEM_BYTES (2*GRU_STAGE*2)   // 71,680 B

__device__ __forceinline__ void gbar(unsigned& gen)
{
    __syncthreads();
    if (threadIdx.x == 0) {
        __threadfence();
        atomicAdd(&g_bar, 1u);
        gen += GRID;
        while (atomicAdd(&g_bar, 0u) < gen) {}
        __threadfence();
    }
    __syncthreads();
}

__global__ void __launch_bounds__(NTHR) decode_persistent(
    const float* __restrict__ bh2h, const float* __restrict__ wscore,
    const float* __restrict__ bih,  const float* __restrict__ bhh)
{
    extern __shared__ __align__(16) unsigned char dynsmem[];
    __shared__ __align__(16) float s_hp[HDIM];
    __shared__ __align__(16) float s_w[HDIM];
    __shared__ __align__(16) float s_h[HDIM];
    __shared__ __align__(16) float2 s_red2[2][256];
    __shared__ float s_e[NTIME];
    __shared__ float red[16];

    const int bid = blockIdx.x;
    const int tid = threadIdx.x;
    const int warp = tid >> 5, lane = tid & 31;
    const int gid = lane >> 2, tig = lane & 3;
    unsigned gen = 0;

    if (tid < 128) ((float4*)s_w)[tid] = ((const float4*)wscore)[tid];
    s_hp[tid] = bh2h[tid];            // h0 = 0 -> hp = bh2h
    float hprev = 0.f;                // h[bid][tid], register-resident
    const float bih_r  = bih[tid];
    const float bih_z  = bih[HDIM + tid];
    const float bih_n  = bih[2*HDIM + tid];
    const float bhh_r  = bhh[tid];
    const float bhh_z  = bhh[HDIM + tid];
    const float bhh_n  = bhh[2*HDIM + tid];

    // ---------- phase C setup (gru partial GEMM) ----------
    const int c_tile = bid >> 1;                // 64 tiles (2 M x 32 N)
    const int c_kz   = bid & 1;
    const int c_mb   = (c_tile >> 5) * 64;
    const int c_nb   = (c_tile & 31) * 16;
    const int c_k0   = c_kz * 256;
    const int c_aside = warp >> 3;              // 0: gi (A=ctx), 1: gh (A=h)
    const int c_wsub = warp & 7;
    const int c_m4 = c_wsub >> 1;
    const int c_nh = c_wsub & 1;
    const int c_aRow = c_m4*16 + (lane & 15);
    const int c_aCol = (lane >> 4) * 8;
    const int c_offAhi = (c_aside*2)*(64*SAS) + c_aRow*SAS + c_aCol;
    const int c_offAlo = c_offAhi + 64*SAS;
    const int c_brow = c_nh*8 + (lane & 7);
    const int c_bmat = (lane >> 3) & 1;
    int c_offBh[3], c_offBl[3];
    #pragma unroll
    for (int g = 0; g < 3; g++) {
        c_offBh[g] = GRU_A_ELE + ((c_aside*3 + g)*2)*(16*SAS) + c_brow*SAS + c_bmat*8;
        c_offBl[g] = c_offBh[g] + 16*SAS;
    }
    uint32_t smem0 = (uint32_t)__cvta_generic_to_shared(dynsmem);
    __syncthreads();

    for (int step = 0; step < NSTEPS; step++) {
        // =============== PHASE B: attention (hp from own s_hp) =================
        {
            const int b = bid;
            float hv[16], wv[16];
            #pragma unroll
            for (int jj = 0; jj < 2; jj++) {
                const int idx = lane + jj*32;
                #pragma unroll
                for (int q = 0; q < 8; q++) {
                    hv[jj*8 + q] = s_hp[idx*8 + q];
                    wv[jj*8 + q] = s_w[idx*8 + q];
                }
            }

            #pragma unroll
            for (int it = 0; it < 16; it++) {
                const int t = warp + (it << 4);
                const uint4* row4 = (const uint4*)(g_fp16 + ((size_t)b * NTIME + t) * HDIM);
                float p = 0.f;
                #pragma unroll
                for (int jj = 0; jj < 2; jj++) {
                    const uint4 v = row4[lane + jj*32];
                    const __half2* vh = (const __half2*)&v;
                    #pragma unroll
                    for (int q = 0; q < 4; q++) {
                        float2 f = __half22float2(vh[q]);
                        p = fmaf(wv[jj*8 + 2*q],     tanh_ap(f.x + hv[jj*8 + 2*q]),     p);
                        p = fmaf(wv[jj*8 + 2*q + 1], tanh_ap(f.y + hv[jj*8 + 2*q + 1]), p);
                    }
                }
                p = warp_sum(p);
                if (lane == 0) s_e[t] = p;
            }
            __syncthreads();

            float v = (tid < NTIME) ? s_e[tid] : -1e30f;
            float m = warp_max(v);
            if (lane == 0) red[warp] = m;
            __syncthreads();
            if (warp == 0) {
                float x = (lane < 16) ? red[lane] : -1e30f;
                x = warp_max(x);
                if (lane == 0) red[0] = x;
            }
            __syncthreads();
            const float mx = red[0];
            __syncthreads();
            float ex = (tid < NTIME) ? __expf(v - mx) : 0.f;
            float s = warp_sum(ex);
            if (lane == 0) red[warp] = s;
            __syncthreads();
            if (warp == 0) {
                float x = (lane < 16) ? red[lane] : 0.f;
                x = warp_sum(x);
                if (lane == 0) red[0] = x;
            }
            __syncthreads();
            const float inv = 1.f / red[0];
            if (tid < NTIME) s_e[tid] = ex * inv;
            __syncthreads();

            float av[8];
            #pragma unroll
            for (int q = 0; q < 8; q++) av[q] = s_e[lane*8 + q];

            #pragma unroll
            for (int ic = 0; ic < 32; ic++) {
                const int c = warp + (ic << 4);
                const uint4 v4 = ((const uint4*)(g_f16ctx + ((size_t)b * NCH + c) * NTIME))[lane];
                const __half2* vh = (const __half2*)&v4;
                float p = 0.f;
                #pragma unroll
                for (int q = 0; q < 4; q++) {
                    float2 f = __half22float2(vh[q]);
                    p = fmaf(f.x, av[2*q],     p);
                    p = fmaf(f.y, av[2*q + 1], p);
                }
                p = warp_sum(p);
                if (lane == 0) {
                    __nv_bfloat16 h, l;
                    split_val(p, h, l);
                    g_ctx_h[b*NCH + c] = h;
                    g_ctx_l[b*NCH + c] = l;
                }
            }
        }
        gbar(gen);

        // =============== PHASE C: gru partial =================
        {
            const __nv_bfloat16* aptr[4] = { g_ctx_h, g_ctx_l, g_h_h, g_h_l };
            float acc[3][4];
            #pragma unroll
            for (int g = 0; g < 3; g++)
                #pragma unroll
                for (int q = 0; q < 4; q++) acc[g][q] = 0.f;

            auto issueC = [&](int kt, int buf) {
                __nv_bfloat16* base = (__nv_bfloat16*)dynsmem + buf * GRU_STAGE;
                #pragma unroll
                for (int i = tid; i < 1792; i += NTHR) {
                    const __nv_bfloat16* src;
                    __nv_bfloat16* dst;
                    if (i < 1024) {
                        const int chunk = i & 3;
                        const int rowid = i >> 2;
                        const int set = rowid >> 6, r = rowid & 63;
                        src = aptr[set] + (size_t)(c_mb + r) * HDIM + kt + chunk*8;
                        dst = base + set*(64*SAS) + r*SAS + chunk*8;
                    } else {
                        const int j = i - 1024;
                        const int chunk = j & 3;
                        const int rowid = j >> 2;     // 0..191
                        const int set = rowid >> 4, r = rowid & 15;
                        const int gate = set >> 1, hl = set & 1;
                        const __nv_bfloat16* wsrc = (gate < 3) ? (hl ? g_Wih_l : g_Wih_h)
                                                               : (hl ? g_Whh_l : g_Whh_h);
                        const int grow = ((gate < 3) ? gate : (gate - 3)) * HDIM + c_nb + r;
                        src = wsrc + (size_t)grow * HDIM + kt + chunk*8;
                        dst = base + GRU_A_ELE + set*(16*SAS) + r*SAS + chunk*8;
                    }
                    cp16cg(dst, src);
                }
                cp_commit();
            };

            issueC(c_k0, 0);
            #pragma unroll 1
            for (int it = 0; it < 8; it++) {
                if (it + 1 < 8) { issueC(c_k0 + (it + 1) * 32, (it + 1) & 1); cp_wait1(); }
                else cp_wait0();
                __syncthreads();
                const uint32_t sb = smem0 + (uint32_t)((it & 1) * GRU_STAGE) * 2u;
                #pragma unroll
                for (int kk = 0; kk < 32; kk += 16) {
                    uint32_t ah[4], al[4];
                    ldsm_x4(ah[0], ah[1], ah[2], ah[3], sb + (c_offAhi + kk)*2);
                    ldsm_x4(al[0], al[1], al[2], al[3], sb + (c_offAlo + kk)*2);
                    #pragma unroll
                    for (int g = 0; g < 3; g++) {
                        uint32_t bh0, bh1, bl0, bl1;
                        ldsm_x2(bh0, bh1, sb + (c_offBh[g] + kk)*2);
                        ldsm_x2(bl0, bl1, sb + (c_offBl[g] + kk)*2);
                        mma16816(acc[g], ah[0], ah[1], ah[2], ah[3], bh0, bh1);
                        mma16816(acc[g], ah[0], ah[1], ah[2], ah[3], bl0, bl1);
                        mma16816(acc[g], al[0], al[1], al[2], al[3], bh0, bh1);
                    }
                }
                __syncthreads();
            }

            const int row = c_mb + c_m4*16 + gid;
            const int col = c_nb + c_nh*8 + tig*2;
            #pragma unroll
            for (int g = 0; g < 3; g++) {
                const int gg = c_aside*3 + g;
                float* dst = &g_gpart[((c_kz*6 + gg)*NBAT)*HDIM];
                dst[(row    )*HDIM + col    ] = acc[g][0];
                dst[(row    )*HDIM + col + 1] = acc[g][1];
                dst[(row + 8)*HDIM + col    ] = acc[g][2];
                dst[(row + 8)*HDIM + col + 1] = acc[g][3];
            }
        }
        gbar(gen);

        // =============== PHASE D: GRU epilogue + hp GEMV (row = bid) =================
        {
            const int row = bid;
            const int j = tid;
            float gsum[6];
            #pragma unroll
            for (int g = 0; g < 6; g++)
                gsum[g] = __ldcg(&g_gpart[((0*6 + g)*NBAT + row)*HDIM + j])
                        + __ldcg(&g_gpart[((1*6 + g)*NBAT + row)*HDIM + j]);
            const float r = 1.f / (1.f + __expf(-(gsum[0] + bih_r + gsum[3] + bhh_r)));
            const float z = 1.f / (1.f + __expf(-(gsum[1] + bih_z + gsum[4] + bhh_z)));
            const float n = tanhf(gsum[2] + bih_n + r * (gsum[5] + bhh_n));
            const float hnew = (1.f - z) * n + z * hprev;
            hprev = hnew;
            s_h[j] = hnew;
            __nv_bfloat16 hh, hl;
            split_val(hnew, hh, hl);
            g_h_h[row*HDIM + j] = hh;
            g_h_l[row*HDIM + j] = hl;
            const size_t o = ((size_t)(row*NSTEPS + step)) * HDIM + j;
            g_hid_h[o] = hh;
            g_hid_l[o] = hl;
            __syncthreads();

            // hp GEMV: s_hp[j] = bh2h[j] + sum_k s_h[k] * Wh2hT[k][j]
            const int jp = tid & 255;
            const int kh = tid >> 8;
            const __half2* W2 = ((const __half2*)g_Wh2hT16) + (size_t)(kh*256)*256 + jp;
            float ax = 0.f, ay = 0.f;
            #pragma unroll 8
            for (int k = 0; k < 256; k++) {
                const float hv = s_h[kh*256 + k];
                const float2 w = __half22float2(W2[(size_t)k*256]);
                ax = fmaf(hv, w.x, ax);
                ay = fmaf(hv, w.y, ay);
            }
            s_red2[kh][jp] = make_float2(ax, ay);
            __syncthreads();
            if (tid < 256) {
                const float2 r0 = s_red2[0][tid];
                const float2 r1 = s_red2[1][tid];
                s_hp[2*tid    ] = r0.x + r1.x + bh2h[2*tid];
                s_hp[2*tid + 1] = r0.y + r1.y + bh2h[2*tid + 1];
            }
            __syncthreads();
        }
        // NO barrier here: D(s) writes (h, hid) are consumed only by C(s+1),
        // which every block reaches strictly after the post-B barrier of step s+1,
        // and that barrier is reached only after ALL blocks finished D(s).
    }
}

// ------------------------- host -------------------------
template <typename T>
static T* sym(const void* s)
{
    void* p = nullptr;
    cudaGetSymbolAddress(&p, s);
    return (T*)p;
}

extern "C" void kernel_launch(void* const* d_in, const int* in_sizes, int n_in,
                              void* d_out, int out_size)
{
    const float* feats  = (const float*)d_in[0];
    const float* Wi2h   = (const float*)d_in[2];
    const float* Wh2h   = (const float*)d_in[3];
    const float* bh2h   = (const float*)d_in[4];
    const float* Wscore = (const float*)d_in[5];
    const float* Wih    = (const float*)d_in[6];
    const float* Whh    = (const float*)d_in[7];
    const float* bih    = (const float*)d_in[8];
    const float* bhh    = (const float*)d_in[9];
    const float* Wgen   = (const float*)d_in[10];
    const float* bgen   = (const float*)d_in[11];
    float* out = (float*)d_out;

    __half* A0f16   = sym<__half>(g_A0f16);
    __half* Wi2h16  = sym<__half>(g_Wi2h16);
    __half* fp16    = sym<__half>(g_fp16);
    __nv_bfloat16* Wgen_h = sym<__nv_bfloat16>(g_Wgen_h);
    __nv_bfloat16* Wgen_l = sym<__nv_bfloat16>(g_Wgen_l);
    __nv_bfloat16* hidh   = sym<__nv_bfloat16>(g_hid_h);
    __nv_bfloat16* hidl   = sym<__nv_bfloat16>(g_hid_l);

    cudaFuncSetAttribute(decode_persistent, cudaFuncAttributeMaxDynamicSharedMemorySize, PSMEM_BYTES);

    // ---- prologue ----
    {
        const int total = HDIM*NCH + HDIM*HDIM + 3*HDIM*NCH + 3*HDIM*HDIM + NOUT*HDIM;
        fused_split<<<(total + 255)/256, 256>>>(Wi2h, Wh2h, Wih, Whh, Wgen);
    }
    transpose_kernel<<<dim3(BT/32, NCH/32), dim3(32, 8)>>>(feats);
    feats16_zero_kernel<<<(int)(((size_t)NBAT*NCH*NTIME)/256), 256>>>(feats);

    // ---- GEMM0 ----
    gemm_f16b<<<dim3(HDIM/128, BT/128), 128>>>(A0f16, Wi2h16, fp16, BT, HDIM, NCH);

    // ---- persistent decode ----
    decode_persistent<<<GRID, NTHR, PSMEM_BYTES>>>(bh2h, Wscore, bih, bhh);

    // ---- generator ----
    gemm_x3<<<dim3((NOUT + 63)/64, (NBAT*NSTEPS)/64), 256>>>(
        hidh, hidl, Wgen_h, Wgen_l, out, bgen, NBAT*NSTEPS, NOUT, HDIM);
}

// round 14
// speedup vs baseline: 1.2499x; 1.2499x over previous
#include <cuda_runtime.h>
#include <cuda_bf16.h>
#include <cuda_fp16.h>
#include <cstdint>
#include <cstddef>

#define NBAT 128
#define NTIME 256
#define NCH 512
#define HDIM 512
#define BT (NBAT*NTIME)
#define NSTEPS 32
#define NOUT 96
#define GRID 128
#define NTHR 512
#define SAS 40

// ------------------------- device scratch -------------------------
__device__ __align__(16) __half g_fp16[(size_t)BT*HDIM];          // feats_proj fp16 [b][t][h]
__device__ __align__(16) __half g_f16ctx[(size_t)NBAT*NCH*NTIME]; // feats fp16 [b][c][t]
__device__ __align__(16) __half g_A0f16[(size_t)BT*NCH];
__device__ __align__(16) __half g_Wi2h16[HDIM*NCH];
__device__ __align__(16) __half g_Wh2h16[HDIM*HDIM];
__device__ __align__(16) __half g_h16[NBAT*HDIM];
__device__ float g_h_f[NBAT*HDIM];
__device__ __align__(16) __nv_bfloat16 g_h_h[NBAT*HDIM], g_h_l[NBAT*HDIM];
__device__ __align__(16) __nv_bfloat16 g_Wih_h[3*HDIM*NCH],  g_Wih_l[3*HDIM*NCH];
__device__ __align__(16) __nv_bfloat16 g_Whh_h[3*HDIM*HDIM], g_Whh_l[3*HDIM*HDIM];
__device__ __align__(16) __nv_bfloat16 g_Wgen_h[NOUT*HDIM],  g_Wgen_l[NOUT*HDIM];
__device__ __align__(16) __nv_bfloat16 g_ctx_h[NBAT*NCH], g_ctx_l[NBAT*NCH];
__device__ __align__(16) __nv_bfloat16 g_hid_h[(size_t)NBAT*NSTEPS*HDIM];
__device__ __align__(16) __nv_bfloat16 g_hid_l[(size_t)NBAT*NSTEPS*HDIM];
__device__ float g_hpart[8*NBAT*HDIM];        // hp K-split partials
__device__ float g_gpart[2*6*NBAT*HDIM];      // [kz][gate][row][col]
__device__ unsigned g_bar;

// ------------------------- helpers -------------------------
__device__ __forceinline__ void mma16816(float* c,
    uint32_t a0, uint32_t a1, uint32_t a2, uint32_t a3, uint32_t b0, uint32_t b1)
{
    asm volatile(
        "mma.sync.aligned.m16n8k16.row.col.f32.bf16.bf16.f32 "
        "{%0,%1,%2,%3}, {%4,%5,%6,%7}, {%8,%9}, {%0,%1,%2,%3};\n"
        : "+f"(c[0]), "+f"(c[1]), "+f"(c[2]), "+f"(c[3])
        : "r"(a0), "r"(a1), "r"(a2), "r"(a3), "r"(b0), "r"(b1));
}

__device__ __forceinline__ void mma16816_f16(float* c,
    uint32_t a0, uint32_t a1, uint32_t a2, uint32_t a3, uint32_t b0, uint32_t b1)
{
    asm volatile(
        "mma.sync.aligned.m16n8k16.row.col.f32.f16.f16.f32 "
        "{%0,%1,%2,%3}, {%4,%5,%6,%7}, {%8,%9}, {%0,%1,%2,%3};\n"
        : "+f"(c[0]), "+f"(c[1]), "+f"(c[2]), "+f"(c[3])
        : "r"(a0), "r"(a1), "r"(a2), "r"(a3), "r"(b0), "r"(b1));
}

__device__ __forceinline__ void ldsm_x4(uint32_t& r0, uint32_t& r1, uint32_t& r2, uint32_t& r3,
                                        uint32_t addr)
{
    asm volatile("ldmatrix.sync.aligned.m8n8.x4.shared.b16 {%0,%1,%2,%3}, [%4];"
        : "=r"(r0), "=r"(r1), "=r"(r2), "=r"(r3) : "r"(addr));
}

__device__ __forceinline__ void ldsm_x2(uint32_t& r0, uint32_t& r1, uint32_t addr)
{
    asm volatile("ldmatrix.sync.aligned.m8n8.x2.shared.b16 {%0,%1}, [%2];"
        : "=r"(r0), "=r"(r1) : "r"(addr));
}

__device__ __forceinline__ void split_val(float v, __nv_bfloat16& hi, __nv_bfloat16& lo)
{
    hi = __float2bfloat16_rn(v);
    lo = __float2bfloat16_rn(v - __bfloat162float(hi));
}

__device__ __forceinline__ float warp_sum(float v)
{
    #pragma unroll
    for (int o = 16; o > 0; o >>= 1) v += __shfl_xor_sync(0xffffffffu, v, o);
    return v;
}

__device__ __forceinline__ float warp_max(float v)
{
    #pragma unroll
    for (int o = 16; o > 0; o >>= 1) v = fmaxf(v, __shfl_xor_sync(0xffffffffu, v, o));
    return v;
}

__device__ __forceinline__ float tanh_ap(float x)
{
    float y;
    asm("tanh.approx.f32 %0, %1;" : "=f"(y) : "f"(x));
    return y;
}

__device__ __forceinline__ void cp16(void* d, const void* s)     // .ca
{
    uint32_t ds = (uint32_t)__cvta_generic_to_shared(d);
    asm volatile("cp.async.ca.shared.global [%0], [%1], 16;\n" :: "r"(ds), "l"(s));
}
__device__ __forceinline__ void cp16cg(void* d, const void* s)   // .cg (cross-phase)
{
    uint32_t ds = (uint32_t)__cvta_generic_to_shared(d);
    asm volatile("cp.async.cg.shared.global [%0], [%1], 16;\n" :: "r"(ds), "l"(s));
}
__device__ __forceinline__ void cp_commit() { asm volatile("cp.async.commit_group;\n"); }
__device__ __forceinline__ void cp_wait1()  { asm volatile("cp.async.wait_group 1;\n"); }
__device__ __forceinline__ void cp_wait0()  { asm volatile("cp.async.wait_group 0;\n"); }

// ------------------------- prologue -------------------------
__global__ void fused_split(const float* __restrict__ W0, const float* __restrict__ W1,
                            const float* __restrict__ W2, const float* __restrict__ W3,
                            const float* __restrict__ W4)
{
    const int n0 = HDIM*NCH;
    const int n1 = n0 + HDIM*HDIM;
    const int n2 = n1 + 3*HDIM*NCH;
    const int n3 = n2 + 3*HDIM*HDIM;
    const int n4 = n3 + NOUT*HDIM;
    int i = blockIdx.x * 256 + threadIdx.x;
    if (i >= n4) return;
    if (i < n0)      { g_Wi2h16[i] = __float2half(W0[i]); return; }
    if (i < n1)      { g_Wh2h16[i - n0] = __float2half(W1[i - n0]); return; }
    const float* src; __nv_bfloat16 *dh, *dl; int off;
    if (i < n2)      { src = W2; dh = g_Wih_h;  dl = g_Wih_l;  off = i - n1; }
    else if (i < n3) { src = W3; dh = g_Whh_h;  dl = g_Whh_l;  off = i - n2; }
    else             { src = W4; dh = g_Wgen_h; dl = g_Wgen_l; off = i - n3; }
    __nv_bfloat16 h, l;
    split_val(src[off], h, l);
    dh[off] = h; dl[off] = l;
}

__global__ void transpose_kernel(const float* __restrict__ feats)
{
    __shared__ float tile[32][33];
    int m0 = blockIdx.x * 32;
    int c0 = blockIdx.y * 32;
    int tx = threadIdx.x, ty = threadIdx.y;
    #pragma unroll
    for (int i = ty; i < 32; i += 8)
        tile[i][tx] = feats[(size_t)(c0 + i) * BT + m0 + tx];
    __syncthreads();
    #pragma unroll
    for (int i = ty; i < 32; i += 8)
        g_A0f16[(size_t)(m0 + i) * NCH + c0 + tx] = __float2half(tile[tx][i]);
}

__global__ void feats16_zero_kernel(const float* __restrict__ feats)
{
    size_t idx = (size_t)blockIdx.x * 256 + threadIdx.x;
    int t = idx & (NTIME - 1);
    int c = (idx >> 8) & (NCH - 1);
    int b = (int)(idx >> 17);
    g_f16ctx[idx] = __float2half(feats[((size_t)c * NBAT + b) * NTIME + t]);
    if (idx < NBAT*HDIM) {
        g_h_f[idx] = 0.f;
        g_h_h[idx] = __float2bfloat16(0.f);
        g_h_l[idx] = __float2bfloat16(0.f);
        g_h16[idx] = __float2half(0.f);
    }
    if (idx == 0) g_bar = 0u;
}

// ------------------------- GEMM0: fp16, block 128x128, warp 64x64 -------------------------
__global__ void __launch_bounds__(128) gemm_f16b(
    const __half* __restrict__ A, const __half* __restrict__ B,
    __half* __restrict__ C16, int M, int N, int K)
{
    __shared__ __align__(16) __half sA[2][128*SAS], sB[2][128*SAS];

    const int mbase = blockIdx.y * 128;
    const int nbase = blockIdx.x * 128;
    const int tid = threadIdx.x;
    const int warp = tid >> 5, lane = tid & 31;
    const int wm = (warp >> 1) * 64;
    const int wn = (warp & 1) * 64;
    const int gid = lane >> 2, tig = lane & 3;

    const int aRow = wm + (lane & 15);
    const int aCol = (lane >> 4) * 8;
    const int bRow = wn + (lane & 7) + ((lane & 16) ? 8 : 0);
    const int bCol = (lane & 8) ? 8 : 0;

    uint32_t aB[2], bB[2];
    #pragma unroll
    for (int s = 0; s < 2; s++) {
        aB[s] = (uint32_t)__cvta_generic_to_shared(&sA[s][aRow*SAS + aCol]);
        bB[s] = (uint32_t)__cvta_generic_to_shared(&sB[s][bRow*SAS + bCol]);
    }

    float acc[4][8][4];
    #pragma unroll
    for (int a = 0; a < 4; a++)
        #pragma unroll
        for (int b = 0; b < 8; b++)
            #pragma unroll
            for (int c = 0; c < 4; c++) acc[a][b][c] = 0.f;

    const int niter = K / 32;

    auto issue = [&](int kt, int buf) {
        #pragma unroll
        for (int i = tid; i < 1024; i += 128) {
            const int chunk = i & 3;
            const int r = (i >> 2) & 127;
            const int gk = kt + chunk*8;
            if (i < 512) cp16(&sA[buf][r*SAS + chunk*8], &A[(size_t)(mbase + r) * K + gk]);
            else         cp16(&sB[buf][r*SAS + chunk*8], &B[(size_t)(nbase + r) * K + gk]);
        }
        cp_commit();
    };

    issue(0, 0);
    for (int it = 0; it < niter; it++) {
        if (it + 1 < niter) { issue((it + 1) * 32, (it + 1) & 1); cp_wait1(); }
        else cp_wait0();
        __syncthreads();
        const int bf = it & 1;
        #pragma unroll
        for (int kk = 0; kk < 32; kk += 16) {
            uint32_t a[4][4], b[4][4];
            #pragma unroll
            for (int mf = 0; mf < 4; mf++)
                ldsm_x4(a[mf][0], a[mf][1], a[mf][2], a[mf][3], aB[bf] + (mf*16*SAS + kk)*2);
            #pragma unroll
            for (int nf = 0; nf < 4; nf++)
                ldsm_x4(b[nf][0], b[nf][1], b[nf][2], b[nf][3], bB[bf] + (nf*16*SAS + kk)*2);
            #pragma unroll
            for (int mf = 0; mf < 4; mf++) {
                #pragma unroll
                for (int nf = 0; nf < 4; nf++) {
                    mma16816_f16(acc[mf][nf*2    ], a[mf][0], a[mf][1], a[mf][2], a[mf][3], b[nf][0], b[nf][1]);
                    mma16816_f16(acc[mf][nf*2 + 1], a[mf][0], a[mf][1], a[mf][2], a[mf][3], b[nf][2], b[nf][3]);
                }
            }
        }
        __syncthreads();
    }

    #pragma unroll
    for (int mf = 0; mf < 4; mf++) {
        #pragma unroll
        for (int nf = 0; nf < 8; nf++) {
            const int r = mbase + wm + mf*16 + gid;
            const int c = nbase + wn + nf*8 + tig*2;
            C16[(size_t)(r    )*N + c    ] = __float2half(acc[mf][nf][0]);
            C16[(size_t)(r    )*N + c + 1] = __float2half(acc[mf][nf][1]);
            C16[(size_t)(r + 8)*N + c    ] = __float2half(acc[mf][nf][2]);
            C16[(size_t)(r + 8)*N + c + 1] = __float2half(acc[mf][nf][3]);
        }
    }
}

// ------------------------- bf16x3 GEMM (generator) -------------------------
__global__ void __launch_bounds__(256) gemm_x3(
    const __nv_bfloat16* __restrict__ Ah,  const __nv_bfloat16* __restrict__ Al,
    const __nv_bfloat16* __restrict__ Bh,  const __nv_bfloat16* __restrict__ Bl,
    float* __restrict__ C, const float* __restrict__ bias,
    int M, int N, int K)
{
    __shared__ __align__(16) __nv_bfloat16 sAh[2][64*SAS], sAl[2][64*SAS];
    __shared__ __align__(16) __nv_bfloat16 sBh[2][64*SAS], sBl[2][64*SAS];

    const int mbase = blockIdx.y * 64;
    const int nbase = blockIdx.x * 64;
    const int tid = threadIdx.x;
    const int warp = tid >> 5, lane = tid & 31;
    const int wm  = (warp >> 2) * 32;
    const int wn  = (warp & 3) * 16;
    const int gid = lane >> 2, tig = lane & 3;
    const int lr  = tid >> 2;
    const int lc  = (tid & 3) * 8;

    const int nrow = nbase + lr;
    const int nr = (nrow < N) ? nrow : 0;

    float acc[2][2][4];
    #pragma unroll
    for (int a = 0; a < 2; a++)
        #pragma unroll
        for (int b = 0; b < 2; b++)
            #pragma unroll
            for (int c = 0; c < 4; c++) acc[a][b][c] = 0.f;

    const int niter = K / 32;
    {
        cp16(&sAh[0][lr*SAS + lc], &Ah[(size_t)(mbase + lr) * K + lc]);
        cp16(&sAl[0][lr*SAS + lc], &Al[(size_t)(mbase + lr) * K + lc]);
        cp16(&sBh[0][lr*SAS + lc], &Bh[(size_t)nr * K + lc]);
        cp16(&sBl[0][lr*SAS + lc], &Bl[(size_t)nr * K + lc]);
        cp_commit();
    }

    for (int it = 0; it < niter; it++) {
        if (it + 1 < niter) {
            const int buf = (it + 1) & 1;
            const int gk = (it + 1) * 32 + lc;
            cp16(&sAh[buf][lr*SAS + lc], &Ah[(size_t)(mbase + lr) * K + gk]);
            cp16(&sAl[buf][lr*SAS + lc], &Al[(size_t)(mbase + lr) * K + gk]);
            cp16(&sBh[buf][lr*SAS + lc], &Bh[(size_t)nr * K + gk]);
            cp16(&sBl[buf][lr*SAS + lc], &Bl[(size_t)nr * K + gk]);
            cp_commit();
            cp_wait1();
        } else {
            cp_wait0();
        }
        __syncthreads();
        const int bf = it & 1;

        #pragma unroll
        for (int kk = 0; kk < 32; kk += 16) {
            uint32_t ah[2][4], al[2][4];
            #pragma unroll
            for (int mi = 0; mi < 2; mi++) {
                const int r = wm + mi*16 + gid;
                const int c = kk + tig*2;
                ah[mi][0] = *(const uint32_t*)&sAh[bf][(r    )*SAS + c    ];
                ah[mi][1] = *(const uint32_t*)&sAh[bf][(r + 8)*SAS + c    ];
                ah[mi][2] = *(const uint32_t*)&sAh[bf][(r    )*SAS + c + 8];
                ah[mi][3] = *(const uint32_t*)&sAh[bf][(r + 8)*SAS + c + 8];
                al[mi][0] = *(const uint32_t*)&sAl[bf][(r    )*SAS + c    ];
                al[mi][1] = *(const uint32_t*)&sAl[bf][(r + 8)*SAS + c    ];
                al[mi][2] = *(const uint32_t*)&sAl[bf][(r    )*SAS + c + 8];
                al[mi][3] = *(const uint32_t*)&sAl[bf][(r + 8)*SAS + c + 8];
            }
            #pragma unroll
            for (int ni = 0; ni < 2; ni++) {
                const int n = wn + ni*8 + gid;
                const int c = kk + tig*2;
                const uint32_t b0h = *(const uint32_t*)&sBh[bf][n*SAS + c    ];
                const uint32_t b1h = *(const uint32_t*)&sBh[bf][n*SAS + c + 8];
                const uint32_t b0l = *(const uint32_t*)&sBl[bf][n*SAS + c    ];
                const uint32_t b1l = *(const uint32_t*)&sBl[bf][n*SAS + c + 8];
                #pragma unroll
                for (int mi = 0; mi < 2; mi++) {
                    mma16816(acc[mi][ni], ah[mi][0], ah[mi][1], ah[mi][2], ah[mi][3], b0h, b1h);
                    mma16816(acc[mi][ni], ah[mi][0], ah[mi][1], ah[mi][2], ah[mi][3], b0l, b1l);
                    mma16816(acc[mi][ni], al[mi][0], al[mi][1], al[mi][2], al[mi][3], b0h, b1h);
                }
            }
        }
        __syncthreads();
    }

    #pragma unroll
    for (int mi = 0; mi < 2; mi++) {
        #pragma unroll
        for (int ni = 0; ni < 2; ni++) {
            const int r = mbase + wm + mi*16 + gid;
            const int c = nbase + wn + ni*8 + tig*2;
            float b0 = 0.f, b1 = 0.f;
            if (bias != nullptr) {
                if (c     < N) b0 = bias[c];
                if (c + 1 < N) b1 = bias[c + 1];
            }
            if (c < N) {
                C[(size_t)(r    )*N + c] = acc[mi][ni][0] + b0;
                C[(size_t)(r + 8)*N + c] = acc[mi][ni][2] + b0;
            }
            if (c + 1 < N) {
                C[(size_t)(r    )*N + c + 1] = acc[mi][ni][1] + b1;
                C[(size_t)(r + 8)*N + c + 1] = acc[mi][ni][3] + b1;
            }
        }
    }
}

// ------------------------- persistent decode kernel (R12 structure, cheaper barrier poll) -------------------------
#define GRU_A_ELE (4*64*SAS)
#define GRU_B_ELE (12*16*SAS)
#define GRU_STAGE (GRU_A_ELE + GRU_B_ELE)
#define PSMEM_BYTES (2*GRU_STAGE*2)   // 71,680 B

__device__ __forceinline__ void gbar(unsigned& gen)
{
    __syncthreads();
    if (threadIdx.x == 0) {
        __threadfence();
        atomicAdd(&g_bar, 1u);
        gen += GRID;
        // poll with plain L2 reads (no RMW serialization)
        while (*(volatile unsigned*)&g_bar < gen) {}
        __threadfence();
    }
    __syncthreads();
}

__global__ void __launch_bounds__(NTHR) decode_persistent(
    const float* __restrict__ bh2h, const float* __restrict__ wscore,
    const float* __restrict__ bih,  const float* __restrict__ bhh)
{
    extern __shared__ __align__(16) unsigned char dynsmem[];
    __shared__ __align__(16) float s_hp[HDIM];
    __shared__ __align__(16) float s_w[HDIM];
    __shared__ float s_e[NTIME];
    __shared__ float red[16];

    const int bid = blockIdx.x;
    const int tid = threadIdx.x;
    const int warp = tid >> 5, lane = tid & 31;
    const int gid = lane >> 2, tig = lane & 3;
    unsigned gen = 0;

    // load wscore once
    if (tid < 128) ((float4*)s_w)[tid] = ((const float4*)wscore)[tid];

    // ---------- phase A setup (hp partial GEMM) ----------
    const int a_tile = bid >> 3;                // 16 tiles (2 M x 8 N)
    const int a_kz   = bid & 7;
    const int a_mb   = (a_tile >> 3) * 64;
    const int a_nb   = (a_tile & 7) * 64;
    const int a_k0   = a_kz * 64;
    __half* aA = (__half*)dynsmem;              // [2][64*SAS]
    __half* aBm = aA + 2*64*SAS;                // [2][64*SAS]
    const int a_chunk = tid & 3;
    const int a_lr = (tid >> 2) & 63;
    const bool a_isB = tid >= 256;
    const int a_wm = (warp >> 2) * 16;          // 4x4 warp grid of 16x16
    const int a_wn = (warp & 3) * 16;
    const int a_aRow = a_wm + (lane & 15);
    const int a_aCol = (lane >> 4) * 8;
    const int a_bRow = a_wn + (lane & 7) + ((lane & 16) ? 8 : 0);
    const int a_bCol = (lane & 8) ? 8 : 0;
    uint32_t a_aB = (uint32_t)__cvta_generic_to_shared(&aA[a_aRow*SAS + a_aCol]);
    uint32_t a_bB = (uint32_t)__cvta_generic_to_shared(&aBm[a_bRow*SAS + a_bCol]);

    // ---------- phase C setup (gru partial GEMM) ----------
    const int c_tile = bid >> 1;                // 64 tiles (2 M x 32 N)
    const int c_kz   = bid & 1;
    const int c_mb   = (c_tile >> 5) * 64;
    const int c_nb   = (c_tile & 31) * 16;
    const int c_k0   = c_kz * 256;
    const int c_aside = warp >> 3;              // 0: gi (A=ctx), 1: gh (A=h)
    const int c_wsub = warp & 7;
    const int c_m4 = c_wsub >> 1;
    const int c_nh = c_wsub & 1;
    const int c_aRow = c_m4*16 + (lane & 15);
    const int c_aCol = (lane >> 4) * 8;
    const int c_offAhi = (c_aside*2)*(64*SAS) + c_aRow*SAS + c_aCol;
    const int c_offAlo = c_offAhi + 64*SAS;
    const int c_brow = c_nh*8 + (lane & 7);
    const int c_bmat = (lane >> 3) & 1;
    int c_offBh[3], c_offBl[3];
    #pragma unroll
    for (int g = 0; g < 3; g++) {
        c_offBh[g] = GRU_A_ELE + ((c_aside*3 + g)*2)*(16*SAS) + c_brow*SAS + c_bmat*8;
        c_offBl[g] = c_offBh[g] + 16*SAS;
    }
    uint32_t smem0 = (uint32_t)__cvta_generic_to_shared(dynsmem);

    for (int step = 0; step < NSTEPS; step++) {
        // =============== PHASE A: hp partial =================
        {
            const __half* srcb = a_isB ? g_Wh2h16 + (size_t)(a_nb + a_lr)*HDIM
                                       : g_h16    + (size_t)(a_mb + a_lr)*HDIM;
            __half* dstb = (a_isB ? aBm : aA) + a_lr*SAS + a_chunk*8;
            cp16cg(dstb, srcb + a_k0 + a_chunk*8);
            cp_commit();
            float acc[2][4] = {{0.f,0.f,0.f,0.f},{0.f,0.f,0.f,0.f}};
            #pragma unroll
            for (int it = 0; it < 2; it++) {
                if (it == 0) {
                    cp16cg(dstb + 64*SAS, srcb + a_k0 + 32 + a_chunk*8);
                    cp_commit();
                    cp_wait1();
                } else cp_wait0();
                __syncthreads();
                const uint32_t boff = (uint32_t)(it * 64*SAS) * 2u;
                #pragma unroll
                for (int kk = 0; kk < 32; kk += 16) {
                    uint32_t a[4], b[4];
                    ldsm_x4(a[0], a[1], a[2], a[3], a_aB + boff + kk*2);
                    ldsm_x4(b[0], b[1], b[2], b[3], a_bB + boff + kk*2);
                    mma16816_f16(acc[0], a[0], a[1], a[2], a[3], b[0], b[1]);
                    mma16816_f16(acc[1], a[0], a[1], a[2], a[3], b[2], b[3]);
                }
                __syncthreads();
            }
            const int r0 = a_mb + a_wm + gid;
            #pragma unroll
            for (int ni = 0; ni < 2; ni++) {
                const int c0 = a_nb + a_wn + ni*8 + tig*2;
                g_hpart[(a_kz*NBAT + r0    )*HDIM + c0    ] = acc[ni][0];
                g_hpart[(a_kz*NBAT + r0    )*HDIM + c0 + 1] = acc[ni][1];
                g_hpart[(a_kz*NBAT + r0 + 8)*HDIM + c0    ] = acc[ni][2];
                g_hpart[(a_kz*NBAT + r0 + 8)*HDIM + c0 + 1] = acc[ni][3];
            }
        }
        gbar(gen);

        // =============== PHASE B: attention =================
        {
            const int b = bid;
            float hpv = bh2h[tid];
            #pragma unroll
            for (int kz = 0; kz < 8; kz++)
                hpv += __ldcg(&g_hpart[(kz*NBAT + b)*HDIM + tid]);
            s_hp[tid] = hpv;
            __syncthreads();

            float hv[16], wv[16];
            #pragma unroll
            for (int jj = 0; jj < 2; jj++) {
                const int idx = lane + jj*32;
                #pragma unroll
                for (int q = 0; q < 8; q++) {
                    hv[jj*8 + q] = s_hp[idx*8 + q];
                    wv[jj*8 + q] = s_w[idx*8 + q];
                }
            }

            #pragma unroll
            for (int it = 0; it < 16; it++) {
                const int t = warp + (it << 4);
                const uint4* row4 = (const uint4*)(g_fp16 + ((size_t)b * NTIME + t) * HDIM);
                float p = 0.f;
                #pragma unroll
                for (int jj = 0; jj < 2; jj++) {
                    const uint4 v = row4[lane + jj*32];
                    const __half2* vh = (const __half2*)&v;
                    #pragma unroll
                    for (int q = 0; q < 4; q++) {
                        float2 f = __half22float2(vh[q]);
                        p = fmaf(wv[jj*8 + 2*q],     tanh_ap(f.x + hv[jj*8 + 2*q]),     p);
                        p = fmaf(wv[jj*8 + 2*q + 1], tanh_ap(f.y + hv[jj*8 + 2*q + 1]), p);
                    }
                }
                p = warp_sum(p);
                if (lane == 0) s_e[t] = p;
            }
            __syncthreads();

            float v = (tid < NTIME) ? s_e[tid] : -1e30f;
            float m = warp_max(v);
            if (lane == 0) red[warp] = m;
            __syncthreads();
            if (warp == 0) {
                float x = (lane < 16) ? red[lane] : -1e30f;
                x = warp_max(x);
                if (lane == 0) red[0] = x;
            }
            __syncthreads();
            const float mx = red[0];
            __syncthreads();
            float ex = (tid < NTIME) ? __expf(v - mx) : 0.f;
            float s = warp_sum(ex);
            if (lane == 0) red[warp] = s;
            __syncthreads();
            if (warp == 0) {
                float x = (lane < 16) ? red[lane] : 0.f;
                x = warp_sum(x);
                if (lane == 0) red[0] = x;
            }
            __syncthreads();
            const float inv = 1.f / red[0];
            if (tid < NTIME) s_e[tid] = ex * inv;
            __syncthreads();

            float av[8];
            #pragma unroll
            for (int q = 0; q < 8; q++) av[q] = s_e[lane*8 + q];

            #pragma unroll
            for (int ic = 0; ic < 32; ic++) {
                const int c = warp + (ic << 4);
                const uint4 v4 = ((const uint4*)(g_f16ctx + ((size_t)b * NCH + c) * NTIME))[lane];
                const __half2* vh = (const __half2*)&v4;
                float p = 0.f;
                #pragma unroll
                for (int q = 0; q < 4; q++) {
                    float2 f = __half22float2(vh[q]);
                    p = fmaf(f.x, av[2*q],     p);
                    p = fmaf(f.y, av[2*q + 1], p);
                }
                p = warp_sum(p);
                if (lane == 0) {
                    __nv_bfloat16 h, l;
                    split_val(p, h, l);
                    g_ctx_h[b*NCH + c] = h;
                    g_ctx_l[b*NCH + c] = l;
                }
            }
        }
        gbar(gen);

        // =============== PHASE C: gru partial =================
        {
            const __nv_bfloat16* aptr[4] = { g_ctx_h, g_ctx_l, g_h_h, g_h_l };
            float acc[3][4];
            #pragma unroll
            for (int g = 0; g < 3; g++)
                #pragma unroll
                for (int q = 0; q < 4; q++) acc[g][q] = 0.f;

            auto issueC = [&](int kt, int buf) {
                __nv_bfloat16* base = (__nv_bfloat16*)dynsmem + buf * GRU_STAGE;
                #pragma unroll
                for (int i = tid; i < 1792; i += NTHR) {
                    const __nv_bfloat16* src;
                    __nv_bfloat16* dst;
                    if (i < 1024) {
                        const int chunk = i & 3;
                        const int rowid = i >> 2;
                        const int set = rowid >> 6, r = rowid & 63;
                        src = aptr[set] + (size_t)(c_mb + r) * HDIM + kt + chunk*8;
                        dst = base + set*(64*SAS) + r*SAS + chunk*8;
                    } else {
                        const int j = i - 1024;
                        const int chunk = j & 3;
                        const int rowid = j >> 2;     // 0..191
                        const int set = rowid >> 4, r = rowid & 15;
                        const int gate = set >> 1, hl = set & 1;
                        const __nv_bfloat16* wsrc = (gate < 3) ? (hl ? g_Wih_l : g_Wih_h)
                                                               : (hl ? g_Whh_l : g_Whh_h);
                        const int grow = ((gate < 3) ? gate : (gate - 3)) * HDIM + c_nb + r;
                        src = wsrc + (size_t)grow * HDIM + kt + chunk*8;
                        dst = base + GRU_A_ELE + set*(16*SAS) + r*SAS + chunk*8;
                    }
                    cp16cg(dst, src);
                }
                cp_commit();
            };

            issueC(c_k0, 0);
            #pragma unroll 1
            for (int it = 0; it < 8; it++) {
                if (it + 1 < 8) { issueC(c_k0 + (it + 1) * 32, (it + 1) & 1); cp_wait1(); }
                else cp_wait0();
                __syncthreads();
                const uint32_t sb = smem0 + (uint32_t)((it & 1) * GRU_STAGE) * 2u;
                #pragma unroll
                for (int kk = 0; kk < 32; kk += 16) {
                    uint32_t ah[4], al[4];
                    ldsm_x4(ah[0], ah[1], ah[2], ah[3], sb + (c_offAhi + kk)*2);
                    ldsm_x4(al[0], al[1], al[2], al[3], sb + (c_offAlo + kk)*2);
                    #pragma unroll
                    for (int g = 0; g < 3; g++) {
                        uint32_t bh0, bh1, bl0, bl1;
                        ldsm_x2(bh0, bh1, sb + (c_offBh[g] + kk)*2);
                        ldsm_x2(bl0, bl1, sb + (c_offBl[g] + kk)*2);
                        mma16816(acc[g], ah[0], ah[1], ah[2], ah[3], bh0, bh1);
                        mma16816(acc[g], ah[0], ah[1], ah[2], ah[3], bl0, bl1);
                        mma16816(acc[g], al[0], al[1], al[2], al[3], bh0, bh1);
                    }
                }
                __syncthreads();
            }

            const int row = c_mb + c_m4*16 + gid;
            const int col = c_nb + c_nh*8 + tig*2;
            #pragma unroll
            for (int g = 0; g < 3; g++) {
                const int gg = c_aside*3 + g;
                float* dst = &g_gpart[((c_kz*6 + gg)*NBAT)*HDIM];
                dst[(row    )*HDIM + col    ] = acc[g][0];
                dst[(row    )*HDIM + col + 1] = acc[g][1];
                dst[(row + 8)*HDIM + col    ] = acc[g][2];
                dst[(row + 8)*HDIM + col + 1] = acc[g][3];
            }
        }
        gbar(gen);

        // =============== PHASE D: GRU epilogue =================
        {
            const int row = bid;
            const int j = tid;
            float gsum[6];
            #pragma unroll
            for (int g = 0; g < 6; g++)
                gsum[g] = __ldcg(&g_gpart[((0*6 + g)*NBAT + row)*HDIM + j])
                        + __ldcg(&g_gpart[((1*6 + g)*NBAT + row)*HDIM + j]);
            const float ir  = gsum[0] + bih[j];
            const float iz  = gsum[1] + bih[HDIM + j];
            const float in_ = gsum[2] + bih[2*HDIM + j];
            const float hr  = gsum[3] + bhh[j];
            const float hz  = gsum[4] + bhh[HDIM + j];
            const float hn  = gsum[5] + bhh[2*HDIM + j];
            const float r = 1.f / (1.f + __expf(-(ir + hr)));
            const float z = 1.f / (1.f + __expf(-(iz + hz)));
            const float n = tanhf(in_ + r * hn);
            const float hprev = g_h_f[row*HDIM + j];
            const float hnew = (1.f - z) * n + z * hprev;
            g_h_f[row*HDIM + j] = hnew;
            g_h16[row*HDIM + j] = __float2half(hnew);
            __nv_bfloat16 hh, hl;
            split_val(hnew, hh, hl);
            g_h_h[row*HDIM + j] = hh;
            g_h_l[row*HDIM + j] = hl;
            const size_t o = ((size_t)(row*NSTEPS + step)) * HDIM + j;
            g_hid_h[o] = hh;
            g_hid_l[o] = hl;
        }
        gbar(gen);
    }
}

// ------------------------- host -------------------------
template <typename T>
static T* sym(const void* s)
{
    void* p = nullptr;
    cudaGetSymbolAddress(&p, s);
    return (T*)p;
}

extern "C" void kernel_launch(void* const* d_in, const int* in_sizes, int n_in,
                              void* d_out, int out_size)
{
    const float* feats  = (const float*)d_in[0];
    const float* Wi2h   = (const float*)d_in[2];
    const float* Wh2h   = (const float*)d_in[3];
    const float* bh2h   = (const float*)d_in[4];
    const float* Wscore = (const float*)d_in[5];
    const float* Wih    = (const float*)d_in[6];
    const float* Whh    = (const float*)d_in[7];
    const float* bih    = (const float*)d_in[8];
    const float* bhh    = (const float*)d_in[9];
    const float* Wgen   = (const float*)d_in[10];
    const float* bgen   = (const float*)d_in[11];
    float* out = (float*)d_out;

    __half* A0f16   = sym<__half>(g_A0f16);
    __half* Wi2h16  = sym<__half>(g_Wi2h16);
    __half* fp16    = sym<__half>(g_fp16);
    __nv_bfloat16* Wgen_h = sym<__nv_bfloat16>(g_Wgen_h);
    __nv_bfloat16* Wgen_l = sym<__nv_bfloat16>(g_Wgen_l);
    __nv_bfloat16* hidh   = sym<__nv_bfloat16>(g_hid_h);
    __nv_bfloat16* hidl   = sym<__nv_bfloat16>(g_hid_l);

    cudaFuncSetAttribute(decode_persistent, cudaFuncAttributeMaxDynamicSharedMemorySize, PSMEM_BYTES);

    // ---- prologue ----
    {
        const int total = HDIM*NCH + HDIM*HDIM + 3*HDIM*NCH + 3*HDIM*HDIM + NOUT*HDIM;
        fused_split<<<(total + 255)/256, 256>>>(Wi2h, Wh2h, Wih, Whh, Wgen);
    }
    transpose_kernel<<<dim3(BT/32, NCH/32), dim3(32, 8)>>>(feats);
    feats16_zero_kernel<<<(int)(((size_t)NBAT*NCH*NTIME)/256), 256>>>(feats);

    // ---- GEMM0: block 128x128, warp 64x64 ----
    gemm_f16b<<<dim3(HDIM/128, BT/128), 128>>>(A0f16, Wi2h16, fp16, BT, HDIM, NCH);

    // ---- persistent decode: all 32 steps in one launch ----
    decode_persistent<<<GRID, NTHR, PSMEM_BYTES>>>(bh2h, Wscore, bih, bhh);

    // ---- generator ----
    gemm_x3<<<dim3((NOUT + 63)/64, (NBAT*NSTEPS)/64), 256>>>(
        hidh, hidl, Wgen_h, Wgen_l, out, bgen, NBAT*NSTEPS, NOUT, HDIM);
}

// round 16
// speedup vs baseline: 1.2728x; 1.0183x over previous
#include <cuda_runtime.h>
#include <cuda_bf16.h>
#include <cuda_fp16.h>
#include <cstdint>
#include <cstddef>

#define NBAT 128
#define NTIME 256
#define NCH 512
#define HDIM 512
#define BT (NBAT*NTIME)
#define NSTEPS 32
#define NOUT 96
#define GRID 128
#define NTHR 512
#define SAS 40

// ------------------------- device scratch -------------------------
__device__ __align__(16) __half g_fp16[(size_t)BT*HDIM];          // feats_proj fp16 [b][t][h]
__device__ __align__(16) __half g_f16ctx[(size_t)NBAT*NCH*NTIME]; // feats fp16 [b][c][t]
__device__ __align__(16) __half g_A0f16[(size_t)BT*NCH];
__device__ __align__(16) __half g_Wi2h16[HDIM*NCH];
__device__ __align__(16) __half g_Wh2h16[HDIM*HDIM];
__device__ __align__(16) __half g_h16[NBAT*HDIM];
__device__ float g_h_f[NBAT*HDIM];
__device__ __align__(16) __nv_bfloat16 g_h_h[NBAT*HDIM], g_h_l[NBAT*HDIM];
__device__ __align__(16) __nv_bfloat16 g_Wih_h[3*HDIM*NCH],  g_Wih_l[3*HDIM*NCH];
__device__ __align__(16) __nv_bfloat16 g_Whh_h[3*HDIM*HDIM], g_Whh_l[3*HDIM*HDIM];
__device__ __align__(16) __nv_bfloat16 g_Wgen_h[NOUT*HDIM],  g_Wgen_l[NOUT*HDIM];
__device__ __align__(16) __nv_bfloat16 g_ctx_h[NBAT*NCH], g_ctx_l[NBAT*NCH];
__device__ __align__(16) __nv_bfloat16 g_hid_h[(size_t)NBAT*NSTEPS*HDIM];
__device__ __align__(16) __nv_bfloat16 g_hid_l[(size_t)NBAT*NSTEPS*HDIM];
__device__ float g_hpart[8*NBAT*HDIM];        // hp K-split partials
__device__ float g_gpart[2*6*NBAT*HDIM];      // [kz][gate][row][col]
__device__ unsigned g_bar;

// ------------------------- helpers -------------------------
__device__ __forceinline__ void mma16816(float* c,
    uint32_t a0, uint32_t a1, uint32_t a2, uint32_t a3, uint32_t b0, uint32_t b1)
{
    asm volatile(
        "mma.sync.aligned.m16n8k16.row.col.f32.bf16.bf16.f32 "
        "{%0,%1,%2,%3}, {%4,%5,%6,%7}, {%8,%9}, {%0,%1,%2,%3};\n"
        : "+f"(c[0]), "+f"(c[1]), "+f"(c[2]), "+f"(c[3])
        : "r"(a0), "r"(a1), "r"(a2), "r"(a3), "r"(b0), "r"(b1));
}

__device__ __forceinline__ void mma16816_f16(float* c,
    uint32_t a0, uint32_t a1, uint32_t a2, uint32_t a3, uint32_t b0, uint32_t b1)
{
    asm volatile(
        "mma.sync.aligned.m16n8k16.row.col.f32.f16.f16.f32 "
        "{%0,%1,%2,%3}, {%4,%5,%6,%7}, {%8,%9}, {%0,%1,%2,%3};\n"
        : "+f"(c[0]), "+f"(c[1]), "+f"(c[2]), "+f"(c[3])
        : "r"(a0), "r"(a1), "r"(a2), "r"(a3), "r"(b0), "r"(b1));
}

__device__ __forceinline__ void ldsm_x4(uint32_t& r0, uint32_t& r1, uint32_t& r2, uint32_t& r3,
                                        uint32_t addr)
{
    asm volatile("ldmatrix.sync.aligned.m8n8.x4.shared.b16 {%0,%1,%2,%3}, [%4];"
        : "=r"(r0), "=r"(r1), "=r"(r2), "=r"(r3) : "r"(addr));
}

__device__ __forceinline__ void ldsm_x2(uint32_t& r0, uint32_t& r1, uint32_t addr)
{
    asm volatile("ldmatrix.sync.aligned.m8n8.x2.shared.b16 {%0,%1}, [%2];"
        : "=r"(r0), "=r"(r1) : "r"(addr));
}

__device__ __forceinline__ void split_val(float v, __nv_bfloat16& hi, __nv_bfloat16& lo)
{
    hi = __float2bfloat16_rn(v);
    lo = __float2bfloat16_rn(v - __bfloat162float(hi));
}

__device__ __forceinline__ float warp_sum(float v)
{
    #pragma unroll
    for (int o = 16; o > 0; o >>= 1) v += __shfl_xor_sync(0xffffffffu, v, o);
    return v;
}

__device__ __forceinline__ float warp_max(float v)
{
    #pragma unroll
    for (int o = 16; o > 0; o >>= 1) v = fmaxf(v, __shfl_xor_sync(0xffffffffu, v, o));
    return v;
}

__device__ __forceinline__ __half2 tanh_h2(__half2 x)
{
    uint32_t y, xi = *(uint32_t*)&x;
    asm("tanh.approx.f16x2 %0, %1;" : "=r"(y) : "r"(xi));
    return *(__half2*)&y;
}

__device__ __forceinline__ void cp16(void* d, const void* s)     // .ca
{
    uint32_t ds = (uint32_t)__cvta_generic_to_shared(d);
    asm volatile("cp.async.ca.shared.global [%0], [%1], 16;\n" :: "r"(ds), "l"(s));
}
__device__ __forceinline__ void cp16cg(void* d, const void* s)   // .cg (cross-phase)
{
    uint32_t ds = (uint32_t)__cvta_generic_to_shared(d);
    asm volatile("cp.async.cg.shared.global [%0], [%1], 16;\n" :: "r"(ds), "l"(s));
}
__device__ __forceinline__ void cp_commit() { asm volatile("cp.async.commit_group;\n"); }
__device__ __forceinline__ void cp_wait1()  { asm volatile("cp.async.wait_group 1;\n"); }
__device__ __forceinline__ void cp_wait0()  { asm volatile("cp.async.wait_group 0;\n"); }

// ------------------------- prologue -------------------------
__global__ void fused_split(const float* __restrict__ W0, const float* __restrict__ W1,
                            const float* __restrict__ W2, const float* __restrict__ W3,
                            const float* __restrict__ W4)
{
    const int n0 = HDIM*NCH;
    const int n1 = n0 + HDIM*HDIM;
    const int n2 = n1 + 3*HDIM*NCH;
    const int n3 = n2 + 3*HDIM*HDIM;
    const int n4 = n3 + NOUT*HDIM;
    int i = blockIdx.x * 256 + threadIdx.x;
    if (i >= n4) return;
    if (i < n0)      { g_Wi2h16[i] = __float2half(W0[i]); return; }
    if (i < n1)      { g_Wh2h16[i - n0] = __float2half(W1[i - n0]); return; }
    const float* src; __nv_bfloat16 *dh, *dl; int off;
    if (i < n2)      { src = W2; dh = g_Wih_h;  dl = g_Wih_l;  off = i - n1; }
    else if (i < n3) { src = W3; dh = g_Whh_h;  dl = g_Whh_l;  off = i - n2; }
    else             { src = W4; dh = g_Wgen_h; dl = g_Wgen_l; off = i - n3; }
    __nv_bfloat16 h, l;
    split_val(src[off], h, l);
    dh[off] = h; dl[off] = l;
}

__global__ void transpose_kernel(const float* __restrict__ feats)
{
    __shared__ float tile[32][33];
    int m0 = blockIdx.x * 32;
    int c0 = blockIdx.y * 32;
    int tx = threadIdx.x, ty = threadIdx.y;
    #pragma unroll
    for (int i = ty; i < 32; i += 8)
        tile[i][tx] = feats[(size_t)(c0 + i) * BT + m0 + tx];
    __syncthreads();
    #pragma unroll
    for (int i = ty; i < 32; i += 8)
        g_A0f16[(size_t)(m0 + i) * NCH + c0 + tx] = __float2half(tile[tx][i]);
}

__global__ void feats16_zero_kernel(const float* __restrict__ feats)
{
    size_t idx = (size_t)blockIdx.x * 256 + threadIdx.x;
    int t = idx & (NTIME - 1);
    int c = (idx >> 8) & (NCH - 1);
    int b = (int)(idx >> 17);
    g_f16ctx[idx] = __float2half(feats[((size_t)c * NBAT + b) * NTIME + t]);
    if (idx < NBAT*HDIM) {
        g_h_f[idx] = 0.f;
        g_h_h[idx] = __float2bfloat16(0.f);
        g_h_l[idx] = __float2bfloat16(0.f);
        g_h16[idx] = __float2half(0.f);
    }
    if (idx == 0) g_bar = 0u;
}

// ------------------------- GEMM0: fp16, block 128x128, warp 64x64 -------------------------
__global__ void __launch_bounds__(128) gemm_f16b(
    const __half* __restrict__ A, const __half* __restrict__ B,
    __half* __restrict__ C16, int M, int N, int K)
{
    __shared__ __align__(16) __half sA[2][128*SAS], sB[2][128*SAS];

    const int mbase = blockIdx.y * 128;
    const int nbase = blockIdx.x * 128;
    const int tid = threadIdx.x;
    const int warp = tid >> 5, lane = tid & 31;
    const int wm = (warp >> 1) * 64;
    const int wn = (warp & 1) * 64;
    const int gid = lane >> 2, tig = lane & 3;

    const int aRow = wm + (lane & 15);
    const int aCol = (lane >> 4) * 8;
    const int bRow = wn + (lane & 7) + ((lane & 16) ? 8 : 0);
    const int bCol = (lane & 8) ? 8 : 0;

    uint32_t aB[2], bB[2];
    #pragma unroll
    for (int s = 0; s < 2; s++) {
        aB[s] = (uint32_t)__cvta_generic_to_shared(&sA[s][aRow*SAS + aCol]);
        bB[s] = (uint32_t)__cvta_generic_to_shared(&sB[s][bRow*SAS + bCol]);
    }

    float acc[4][8][4];
    #pragma unroll
    for (int a = 0; a < 4; a++)
        #pragma unroll
        for (int b = 0; b < 8; b++)
            #pragma unroll
            for (int c = 0; c < 4; c++) acc[a][b][c] = 0.f;

    const int niter = K / 32;

    auto issue = [&](int kt, int buf) {
        #pragma unroll
        for (int i = tid; i < 1024; i += 128) {
            const int chunk = i & 3;
            const int r = (i >> 2) & 127;
            const int gk = kt + chunk*8;
            if (i < 512) cp16(&sA[buf][r*SAS + chunk*8], &A[(size_t)(mbase + r) * K + gk]);
            else         cp16(&sB[buf][r*SAS + chunk*8], &B[(size_t)(nbase + r) * K + gk]);
        }
        cp_commit();
    };

    issue(0, 0);
    for (int it = 0; it < niter; it++) {
        if (it + 1 < niter) { issue((it + 1) * 32, (it + 1) & 1); cp_wait1(); }
        else cp_wait0();
        __syncthreads();
        const int bf = it & 1;
        #pragma unroll
        for (int kk = 0; kk < 32; kk += 16) {
            uint32_t a[4][4], b[4][4];
            #pragma unroll
            for (int mf = 0; mf < 4; mf++)
                ldsm_x4(a[mf][0], a[mf][1], a[mf][2], a[mf][3], aB[bf] + (mf*16*SAS + kk)*2);
            #pragma unroll
            for (int nf = 0; nf < 4; nf++)
                ldsm_x4(b[nf][0], b[nf][1], b[nf][2], b[nf][3], bB[bf] + (nf*16*SAS + kk)*2);
            #pragma unroll
            for (int mf = 0; mf < 4; mf++) {
                #pragma unroll
                for (int nf = 0; nf < 4; nf++) {
                    mma16816_f16(acc[mf][nf*2    ], a[mf][0], a[mf][1], a[mf][2], a[mf][3], b[nf][0], b[nf][1]);
                    mma16816_f16(acc[mf][nf*2 + 1], a[mf][0], a[mf][1], a[mf][2], a[mf][3], b[nf][2], b[nf][3]);
                }
            }
        }
        __syncthreads();
    }

    #pragma unroll
    for (int mf = 0; mf < 4; mf++) {
        #pragma unroll
        for (int nf = 0; nf < 8; nf++) {
            const int r = mbase + wm + mf*16 + gid;
            const int c = nbase + wn + nf*8 + tig*2;
            C16[(size_t)(r    )*N + c    ] = __float2half(acc[mf][nf][0]);
            C16[(size_t)(r    )*N + c + 1] = __float2half(acc[mf][nf][1]);
            C16[(size_t)(r + 8)*N + c    ] = __float2half(acc[mf][nf][2]);
            C16[(size_t)(r + 8)*N + c + 1] = __float2half(acc[mf][nf][3]);
        }
    }
}

// ------------------------- bf16x3 GEMM (generator) -------------------------
__global__ void __launch_bounds__(256) gemm_x3(
    const __nv_bfloat16* __restrict__ Ah,  const __nv_bfloat16* __restrict__ Al,
    const __nv_bfloat16* __restrict__ Bh,  const __nv_bfloat16* __restrict__ Bl,
    float* __restrict__ C, const float* __restrict__ bias,
    int M, int N, int K)
{
    __shared__ __align__(16) __nv_bfloat16 sAh[2][64*SAS], sAl[2][64*SAS];
    __shared__ __align__(16) __nv_bfloat16 sBh[2][64*SAS], sBl[2][64*SAS];

    const int mbase = blockIdx.y * 64;
    const int nbase = blockIdx.x * 64;
    const int tid = threadIdx.x;
    const int warp = tid >> 5, lane = tid & 31;
    const int wm  = (warp >> 2) * 32;
    const int wn  = (warp & 3) * 16;
    const int gid = lane >> 2, tig = lane & 3;
    const int lr  = tid >> 2;
    const int lc  = (tid & 3) * 8;

    const int nrow = nbase + lr;
    const int nr = (nrow < N) ? nrow : 0;

    float acc[2][2][4];
    #pragma unroll
    for (int a = 0; a < 2; a++)
        #pragma unroll
        for (int b = 0; b < 2; b++)
            #pragma unroll
            for (int c = 0; c < 4; c++) acc[a][b][c] = 0.f;

    const int niter = K / 32;
    {
        cp16(&sAh[0][lr*SAS + lc], &Ah[(size_t)(mbase + lr) * K + lc]);
        cp16(&sAl[0][lr*SAS + lc], &Al[(size_t)(mbase + lr) * K + lc]);
        cp16(&sBh[0][lr*SAS + lc], &Bh[(size_t)nr * K + lc]);
        cp16(&sBl[0][lr*SAS + lc], &Bl[(size_t)nr * K + lc]);
        cp_commit();
    }

    for (int it = 0; it < niter; it++) {
        if (it + 1 < niter) {
            const int buf = (it + 1) & 1;
            const int gk = (it + 1) * 32 + lc;
            cp16(&sAh[buf][lr*SAS + lc], &Ah[(size_t)(mbase + lr) * K + gk]);
            cp16(&sAl[buf][lr*SAS + lc], &Al[(size_t)(mbase + lr) * K + gk]);
            cp16(&sBh[buf][lr*SAS + lc], &Bh[(size_t)nr * K + gk]);
            cp16(&sBl[buf][lr*SAS + lc], &Bl[(size_t)nr * K + gk]);
            cp_commit();
            cp_wait1();
        } else {
            cp_wait0();
        }
        __syncthreads();
        const int bf = it & 1;

        #pragma unroll
        for (int kk = 0; kk < 32; kk += 16) {
            uint32_t ah[2][4], al[2][4];
            #pragma unroll
            for (int mi = 0; mi < 2; mi++) {
                const int r = wm + mi*16 + gid;
                const int c = kk + tig*2;
                ah[mi][0] = *(const uint32_t*)&sAh[bf][(r    )*SAS + c    ];
                ah[mi][1] = *(const uint32_t*)&sAh[bf][(r + 8)*SAS + c    ];
                ah[mi][2] = *(const uint32_t*)&sAh[bf][(r    )*SAS + c + 8];
                ah[mi][3] = *(const uint32_t*)&sAh[bf][(r + 8)*SAS + c + 8];
                al[mi][0] = *(const uint32_t*)&sAl[bf][(r    )*SAS + c    ];
                al[mi][1] = *(const uint32_t*)&sAl[bf][(r + 8)*SAS + c    ];
                al[mi][2] = *(const uint32_t*)&sAl[bf][(r    )*SAS + c + 8];
                al[mi][3] = *(const uint32_t*)&sAl[bf][(r + 8)*SAS + c + 8];
            }
            #pragma unroll
            for (int ni = 0; ni < 2; ni++) {
                const int n = wn + ni*8 + gid;
                const int c = kk + tig*2;
                const uint32_t b0h = *(const uint32_t*)&sBh[bf][n*SAS + c    ];
                const uint32_t b1h = *(const uint32_t*)&sBh[bf][n*SAS + c + 8];
                const uint32_t b0l = *(const uint32_t*)&sBl[bf][n*SAS + c    ];
                const uint32_t b1l = *(const uint32_t*)&sBl[bf][n*SAS + c + 8];
                #pragma unroll
                for (int mi = 0; mi < 2; mi++) {
                    mma16816(acc[mi][ni], ah[mi][0], ah[mi][1], ah[mi][2], ah[mi][3], b0h, b1h);
                    mma16816(acc[mi][ni], ah[mi][0], ah[mi][1], ah[mi][2], ah[mi][3], b0l, b1l);
                    mma16816(acc[mi][ni], al[mi][0], al[mi][1], al[mi][2], al[mi][3], b0h, b1h);
                }
            }
        }
        __syncthreads();
    }

    #pragma unroll
    for (int mi = 0; mi < 2; mi++) {
        #pragma unroll
        for (int ni = 0; ni < 2; ni++) {
            const int r = mbase + wm + mi*16 + gid;
            const int c = nbase + wn + ni*8 + tig*2;
            float b0 = 0.f, b1 = 0.f;
            if (bias != nullptr) {
                if (c     < N) b0 = bias[c];
                if (c + 1 < N) b1 = bias[c + 1];
            }
            if (c < N) {
                C[(size_t)(r    )*N + c] = acc[mi][ni][0] + b0;
                C[(size_t)(r + 8)*N + c] = acc[mi][ni][2] + b0;
            }
            if (c + 1 < N) {
                C[(size_t)(r    )*N + c + 1] = acc[mi][ni][1] + b1;
                C[(size_t)(r + 8)*N + c + 1] = acc[mi][ni][3] + b1;
            }
        }
    }
}

// ------------------------- persistent decode kernel (R12 structure, f16x2 tanh in B) -------------------------
#define GRU_A_ELE (4*64*SAS)
#define GRU_B_ELE (12*16*SAS)
#define GRU_STAGE (GRU_A_ELE + GRU_B_ELE)
#define PSMEM_BYTES (2*GRU_STAGE*2)   // 71,680 B

__device__ __forceinline__ void gbar(unsigned& gen)
{
    __syncthreads();
    if (threadIdx.x == 0) {
        __threadfence();
        atomicAdd(&g_bar, 1u);
        gen += GRID;
        while (*(volatile unsigned*)&g_bar < gen) {}
        __threadfence();
    }
    __syncthreads();
}

__global__ void __launch_bounds__(NTHR) decode_persistent(
    const float* __restrict__ bh2h, const float* __restrict__ wscore,
    const float* __restrict__ bih,  const float* __restrict__ bhh)
{
    extern __shared__ __align__(16) unsigned char dynsmem[];
    __shared__ __align__(16) float s_hp[HDIM];
    __shared__ __align__(16) float s_w[HDIM];
    __shared__ float s_e[NTIME];
    __shared__ float red[16];

    const int bid = blockIdx.x;
    const int tid = threadIdx.x;
    const int warp = tid >> 5, lane = tid & 31;
    const int gid = lane >> 2, tig = lane & 3;
    unsigned gen = 0;

    if (tid < 128) ((float4*)s_w)[tid] = ((const float4*)wscore)[tid];

    // ---------- phase A setup ----------
    const int a_tile = bid >> 3;
    const int a_kz   = bid & 7;
    const int a_mb   = (a_tile >> 3) * 64;
    const int a_nb   = (a_tile & 7) * 64;
    const int a_k0   = a_kz * 64;
    __half* aA = (__half*)dynsmem;
    __half* aBm = aA + 2*64*SAS;
    const int a_chunk = tid & 3;
    const int a_lr = (tid >> 2) & 63;
    const bool a_isB = tid >= 256;
    const int a_wm = (warp >> 2) * 16;
    const int a_wn = (warp & 3) * 16;
    const int a_aRow = a_wm + (lane & 15);
    const int a_aCol = (lane >> 4) * 8;
    const int a_bRow = a_wn + (lane & 7) + ((lane & 16) ? 8 : 0);
    const int a_bCol = (lane & 8) ? 8 : 0;
    uint32_t a_aB = (uint32_t)__cvta_generic_to_shared(&aA[a_aRow*SAS + a_aCol]);
    uint32_t a_bB = (uint32_t)__cvta_generic_to_shared(&aBm[a_bRow*SAS + a_bCol]);

    // ---------- phase C setup ----------
    const int c_tile = bid >> 1;
    const int c_kz   = bid & 1;
    const int c_mb   = (c_tile >> 5) * 64;
    const int c_nb   = (c_tile & 31) * 16;
    const int c_k0   = c_kz * 256;
    const int c_aside = warp >> 3;
    const int c_wsub = warp & 7;
    const int c_m4 = c_wsub >> 1;
    const int c_nh = c_wsub & 1;
    const int c_aRow = c_m4*16 + (lane & 15);
    const int c_aCol = (lane >> 4) * 8;
    const int c_offAhi = (c_aside*2)*(64*SAS) + c_aRow*SAS + c_aCol;
    const int c_offAlo = c_offAhi + 64*SAS;
    const int c_brow = c_nh*8 + (lane & 7);
    const int c_bmat = (lane >> 3) & 1;
    int c_offBh[3], c_offBl[3];
    #pragma unroll
    for (int g = 0; g < 3; g++) {
        c_offBh[g] = GRU_A_ELE + ((c_aside*3 + g)*2)*(16*SAS) + c_brow*SAS + c_bmat*8;
        c_offBl[g] = c_offBh[g] + 16*SAS;
    }
    uint32_t smem0 = (uint32_t)__cvta_generic_to_shared(dynsmem);

    for (int step = 0; step < NSTEPS; step++) {
        // =============== PHASE A: hp partial =================
        {
            const __half* srcb = a_isB ? g_Wh2h16 + (size_t)(a_nb + a_lr)*HDIM
                                       : g_h16    + (size_t)(a_mb + a_lr)*HDIM;
            __half* dstb = (a_isB ? aBm : aA) + a_lr*SAS + a_chunk*8;
            cp16cg(dstb, srcb + a_k0 + a_chunk*8);
            cp_commit();
            float acc[2][4] = {{0.f,0.f,0.f,0.f},{0.f,0.f,0.f,0.f}};
            #pragma unroll
            for (int it = 0; it < 2; it++) {
                if (it == 0) {
                    cp16cg(dstb + 64*SAS, srcb + a_k0 + 32 + a_chunk*8);
                    cp_commit();
                    cp_wait1();
                } else cp_wait0();
                __syncthreads();
                const uint32_t boff = (uint32_t)(it * 64*SAS) * 2u;
                #pragma unroll
                for (int kk = 0; kk < 32; kk += 16) {
                    uint32_t a[4], b[4];
                    ldsm_x4(a[0], a[1], a[2], a[3], a_aB + boff + kk*2);
                    ldsm_x4(b[0], b[1], b[2], b[3], a_bB + boff + kk*2);
                    mma16816_f16(acc[0], a[0], a[1], a[2], a[3], b[0], b[1]);
                    mma16816_f16(acc[1], a[0], a[1], a[2], a[3], b[2], b[3]);
                }
                __syncthreads();
            }
            const int r0 = a_mb + a_wm + gid;
            #pragma unroll
            for (int ni = 0; ni < 2; ni++) {
                const int c0 = a_nb + a_wn + ni*8 + tig*2;
                g_hpart[(a_kz*NBAT + r0    )*HDIM + c0    ] = acc[ni][0];
                g_hpart[(a_kz*NBAT + r0    )*HDIM + c0 + 1] = acc[ni][1];
                g_hpart[(a_kz*NBAT + r0 + 8)*HDIM + c0    ] = acc[ni][2];
                g_hpart[(a_kz*NBAT + r0 + 8)*HDIM + c0 + 1] = acc[ni][3];
            }
        }
        gbar(gen);

        // =============== PHASE B: attention (f16x2 tanh) =================
        {
            const int b = bid;
            float hpv = bh2h[tid];
            #pragma unroll
            for (int kz = 0; kz < 8; kz++)
                hpv += __ldcg(&g_hpart[(kz*NBAT + b)*HDIM + tid]);
            s_hp[tid] = hpv;
            __syncthreads();

            __half2 hv2[8];
            float wv[16];
            #pragma unroll
            for (int jj = 0; jj < 2; jj++) {
                const int idx = lane + jj*32;
                #pragma unroll
                for (int q = 0; q < 4; q++)
                    hv2[jj*4 + q] = __floats2half2_rn(s_hp[idx*8 + 2*q], s_hp[idx*8 + 2*q + 1]);
                #pragma unroll
                for (int q = 0; q < 8; q++) wv[jj*8 + q] = s_w[idx*8 + q];
            }

            #pragma unroll
            for (int it = 0; it < 16; it++) {
                const int t = warp + (it << 4);
                const uint4* row4 = (const uint4*)(g_fp16 + ((size_t)b * NTIME + t) * HDIM);
                float p = 0.f;
                #pragma unroll
                for (int jj = 0; jj < 2; jj++) {
                    const uint4 v = row4[lane + jj*32];
                    const __half2* vh = (const __half2*)&v;
                    #pragma unroll
                    for (int q = 0; q < 4; q++) {
                        const __half2 th = tanh_h2(__hadd2(vh[q], hv2[jj*4 + q]));
                        const float2 f = __half22float2(th);
                        p = fmaf(wv[jj*8 + 2*q],     f.x, p);
                        p = fmaf(wv[jj*8 + 2*q + 1], f.y, p);
                    }
                }
                p = warp_sum(p);
                if (lane == 0) s_e[t] = p;
            }
            __syncthreads();

            float v = (tid < NTIME) ? s_e[tid] : -1e30f;
            float m = warp_max(v);
            if (lane == 0) red[warp] = m;
            __syncthreads();
            if (warp == 0) {
                float x = (lane < 16) ? red[lane] : -1e30f;
                x = warp_max(x);
                if (lane == 0) red[0] = x;
            }
            __syncthreads();
            const float mx = red[0];
            __syncthreads();
            float ex = (tid < NTIME) ? __expf(v - mx) : 0.f;
            float s = warp_sum(ex);
            if (lane == 0) red[warp] = s;
            __syncthreads();
            if (warp == 0) {
                float x = (lane < 16) ? red[lane] : 0.f;
                x = warp_sum(x);
                if (lane == 0) red[0] = x;
            }
            __syncthreads();
            const float inv = 1.f / red[0];
            if (tid < NTIME) s_e[tid] = ex * inv;
            __syncthreads();

            float av[8];
            #pragma unroll
            for (int q = 0; q < 8; q++) av[q] = s_e[lane*8 + q];

            #pragma unroll
            for (int ic = 0; ic < 32; ic++) {
                const int c = warp + (ic << 4);
                const uint4 v4 = ((const uint4*)(g_f16ctx + ((size_t)b * NCH + c) * NTIME))[lane];
                const __half2* vh = (const __half2*)&v4;
                float p = 0.f;
                #pragma unroll
                for (int q = 0; q < 4; q++) {
                    float2 f = __half22float2(vh[q]);
                    p = fmaf(f.x, av[2*q],     p);
                    p = fmaf(f.y, av[2*q + 1], p);
                }
                p = warp_sum(p);
                if (lane == 0) {
                    __nv_bfloat16 h, l;
                    split_val(p, h, l);
                    g_ctx_h[b*NCH + c] = h;
                    g_ctx_l[b*NCH + c] = l;
                }
            }
        }
        gbar(gen);

        // =============== PHASE C: gru partial =================
        {
            const __nv_bfloat16* aptr[4] = { g_ctx_h, g_ctx_l, g_h_h, g_h_l };
            float acc[3][4];
            #pragma unroll
            for (int g = 0; g < 3; g++)
                #pragma unroll
                for (int q = 0; q < 4; q++) acc[g][q] = 0.f;

            auto issueC = [&](int kt, int buf) {
                __nv_bfloat16* base = (__nv_bfloat16*)dynsmem + buf * GRU_STAGE;
                #pragma unroll
                for (int i = tid; i < 1792; i += NTHR) {
                    const __nv_bfloat16* src;
                    __nv_bfloat16* dst;
                    if (i < 1024) {
                        const int chunk = i & 3;
                        const int rowid = i >> 2;
                        const int set = rowid >> 6, r = rowid & 63;
                        src = aptr[set] + (size_t)(c_mb + r) * HDIM + kt + chunk*8;
                        dst = base + set*(64*SAS) + r*SAS + chunk*8;
                    } else {
                        const int j = i - 1024;
                        const int chunk = j & 3;
                        const int rowid = j >> 2;
                        const int set = rowid >> 4, r = rowid & 15;
                        const int gate = set >> 1, hl = set & 1;
                        const __nv_bfloat16* wsrc = (gate < 3) ? (hl ? g_Wih_l : g_Wih_h)
                                                               : (hl ? g_Whh_l : g_Whh_h);
                        const int grow = ((gate < 3) ? gate : (gate - 3)) * HDIM + c_nb + r;
                        src = wsrc + (size_t)grow * HDIM + kt + chunk*8;
                        dst = base + GRU_A_ELE + set*(16*SAS) + r*SAS + chunk*8;
                    }
                    cp16cg(dst, src);
                }
                cp_commit();
            };

            issueC(c_k0, 0);
            #pragma unroll 1
            for (int it = 0; it < 8; it++) {
                if (it + 1 < 8) { issueC(c_k0 + (it + 1) * 32, (it + 1) & 1); cp_wait1(); }
                else cp_wait0();
                __syncthreads();
                const uint32_t sb = smem0 + (uint32_t)((it & 1) * GRU_STAGE) * 2u;
                #pragma unroll
                for (int kk = 0; kk < 32; kk += 16) {
                    uint32_t ah[4], al[4];
                    ldsm_x4(ah[0], ah[1], ah[2], ah[3], sb + (c_offAhi + kk)*2);
                    ldsm_x4(al[0], al[1], al[2], al[3], sb + (c_offAlo + kk)*2);
                    #pragma unroll
                    for (int g = 0; g < 3; g++) {
                        uint32_t bh0, bh1, bl0, bl1;
                        ldsm_x2(bh0, bh1, sb + (c_offBh[g] + kk)*2);
                        ldsm_x2(bl0, bl1, sb + (c_offBl[g] + kk)*2);
                        mma16816(acc[g], ah[0], ah[1], ah[2], ah[3], bh0, bh1);
                        mma16816(acc[g], ah[0], ah[1], ah[2], ah[3], bl0, bl1);
                        mma16816(acc[g], al[0], al[1], al[2], al[3], bh0, bh1);
                    }
                }
                __syncthreads();
            }

            const int row = c_mb + c_m4*16 + gid;
            const int col = c_nb + c_nh*8 + tig*2;
            #pragma unroll
            for (int g = 0; g < 3; g++) {
                const int gg = c_aside*3 + g;
                float* dst = &g_gpart[((c_kz*6 + gg)*NBAT)*HDIM];
                dst[(row    )*HDIM + col    ] = acc[g][0];
                dst[(row    )*HDIM + col + 1] = acc[g][1];
                dst[(row + 8)*HDIM + col    ] = acc[g][2];
                dst[(row + 8)*HDIM + col + 1] = acc[g][3];
            }
        }
        gbar(gen);

        // =============== PHASE D: GRU epilogue =================
        {
            const int row = bid;
            const int j = tid;
            float gsum[6];
            #pragma unroll
            for (int g = 0; g < 6; g++)
                gsum[g] = __ldcg(&g_gpart[((0*6 + g)*NBAT + row)*HDIM + j])
                        + __ldcg(&g_gpart[((1*6 + g)*NBAT + row)*HDIM + j]);
            const float ir  = gsum[0] + bih[j];
            const float iz  = gsum[1] + bih[HDIM + j];
            const float in_ = gsum[2] + bih[2*HDIM + j];
            const float hr  = gsum[3] + bhh[j];
            const float hz  = gsum[4] + bhh[HDIM + j];
            const float hn  = gsum[5] + bhh[2*HDIM + j];
            const float r = 1.f / (1.f + __expf(-(ir + hr)));
            const float z = 1.f / (1.f + __expf(-(iz + hz)));
            const float n = tanhf(in_ + r * hn);
            const float hprev = g_h_f[row*HDIM + j];
            const float hnew = (1.f - z) * n + z * hprev;
            g_h_f[row*HDIM + j] = hnew;
            g_h16[row*HDIM + j] = __float2half(hnew);
            __nv_bfloat16 hh, hl;
            split_val(hnew, hh, hl);
            g_h_h[row*HDIM + j] = hh;
            g_h_l[row*HDIM + j] = hl;
            const size_t o = ((size_t)(row*NSTEPS + step)) * HDIM + j;
            g_hid_h[o] = hh;
            g_hid_l[o] = hl;
        }
        gbar(gen);
    }
}

// ------------------------- host -------------------------
template <typename T>
static T* sym(const void* s)
{
    void* p = nullptr;
    cudaGetSymbolAddress(&p, s);
    return (T*)p;
}

extern "C" void kernel_launch(void* const* d_in, const int* in_sizes, int n_in,
                              void* d_out, int out_size)
{
    const float* feats  = (const float*)d_in[0];
    const float* Wi2h   = (const float*)d_in[2];
    const float* Wh2h   = (const float*)d_in[3];
    const float* bh2h   = (const float*)d_in[4];
    const float* Wscore = (const float*)d_in[5];
    const float* Wih    = (const float*)d_in[6];
    const float* Whh    = (const float*)d_in[7];
    const float* bih    = (const float*)d_in[8];
    const float* bhh    = (const float*)d_in[9];
    const float* Wgen   = (const float*)d_in[10];
    const float* bgen   = (const float*)d_in[11];
    float* out = (float*)d_out;

    __half* A0f16   = sym<__half>(g_A0f16);
    __half* Wi2h16  = sym<__half>(g_Wi2h16);
    __half* fp16    = sym<__half>(g_fp16);
    __nv_bfloat16* Wgen_h = sym<__nv_bfloat16>(g_Wgen_h);
    __nv_bfloat16* Wgen_l = sym<__nv_bfloat16>(g_Wgen_l);
    __nv_bfloat16* hidh   = sym<__nv_bfloat16>(g_hid_h);
    __nv_bfloat16* hidl   = sym<__nv_bfloat16>(g_hid_l);

    cudaFuncSetAttribute(decode_persistent, cudaFuncAttributeMaxDynamicSharedMemorySize, PSMEM_BYTES);

    // ---- prologue ----
    {
        const int total = HDIM*NCH + HDIM*HDIM + 3*HDIM*NCH + 3*HDIM*HDIM + NOUT*HDIM;
        fused_split<<<(total + 255)/256, 256>>>(Wi2h, Wh2h, Wih, Whh, Wgen);
    }
    transpose_kernel<<<dim3(BT/32, NCH/32), dim3(32, 8)>>>(feats);
    feats16_zero_kernel<<<(int)(((size_t)NBAT*NCH*NTIME)/256), 256>>>(feats);

    // ---- GEMM0 ----
    gemm_f16b<<<dim3(HDIM/128, BT/128), 128>>>(A0f16, Wi2h16, fp16, BT, HDIM, NCH);

    // ---- persistent decode ----
    decode_persistent<<<GRID, NTHR, PSMEM_BYTES>>>(bh2h, Wscore, bih, bhh);

    // ---- generator ----
    gemm_x3<<<dim3((NOUT + 63)/64, (NBAT*NSTEPS)/64), 256>>>(
        hidh, hidl, Wgen_h, Wgen_l, out, bgen, NBAT*NSTEPS, NOUT, HDIM);
}